// round 14
// baseline (speedup 1.0000x reference)
#include <cuda_runtime.h>
#include <cuda_bf16.h>
#include <math.h>

#define HD 128
#define ETILE 256
#define NTILE 64
#define NMAX 20000
#define EMAX 640000

// ---------------- scratch (device globals: allocation-free)
__device__ float g_P[NMAX * HD];
__device__ float g_Q[NMAX * HD];
__device__ float g_mi[NMAX * HD];
__device__ float g_psum[NMAX * 3];
__device__ float g_cnt[NMAX];
// fragment-packed transposed weight images
__device__ __align__(16) unsigned char g_imgW2[65536];  // eW2^T bf16 hi(0)/lo(32768)
__device__ __align__(16) unsigned char g_imgC1[32768];  // cW1^T bf16 hi only

// ---------------- helpers
__device__ __forceinline__ float silu(float x) {
    float hx = 0.5f * x;
    float t;
    asm("tanh.approx.f32 %0, %1;" : "=f"(t) : "f"(hx));
    return fmaf(hx, t, hx);
}

__device__ __forceinline__ unsigned smem_u32(const void* p) {
    unsigned r;
    asm("{ .reg .u64 t; cvta.to.shared.u64 t, %1; cvt.u32.u64 %0, t; }"
        : "=r"(r) : "l"(p));
    return r;
}

__device__ __forceinline__ void red_add_v2(float* p, float a, float b) {
    asm volatile("red.global.add.v2.f32 [%0], {%1, %2};"
                 :: "l"(p), "f"(a), "f"(b) : "memory");
}

__device__ __forceinline__ unsigned bfpack(__nv_bfloat16 a, __nv_bfloat16 b) {
    unsigned short ua = __bfloat16_as_ushort(a), ub = __bfloat16_as_ushort(b);
    return (unsigned)ua | ((unsigned)ub << 16);
}

__device__ __forceinline__ unsigned bfpackf(float a, float b) {
    return bfpack(__float2bfloat16(a), __float2bfloat16(b));
}

__device__ __forceinline__ void bfsplit(float v, __nv_bfloat16& hi, __nv_bfloat16& lo) {
    hi = __float2bfloat16(v);
    lo = __float2bfloat16(v - __bfloat162float(hi));
}

// m16n8k16 row.col f32.bf16.bf16.f32 — standard PTX, valid on base sm_103
__device__ __forceinline__ void mma_bf16(float* c, const uint4& a, const uint2& b) {
    asm volatile(
        "mma.sync.aligned.m16n8k16.row.col.f32.bf16.bf16.f32 "
        "{%0,%1,%2,%3}, {%4,%5,%6,%7}, {%8,%9}, {%0,%1,%2,%3};"
        : "+f"(c[0]), "+f"(c[1]), "+f"(c[2]), "+f"(c[3])
        : "r"(a.x), "r"(a.y), "r"(a.z), "r"(a.w), "r"(b.x), "r"(b.y));
}

// SMEM layout
#define ABLK   528
#define ALO    67584                 // 16*8*528 (hi size)
#define SM_A   0                     // 135168 (hi+lo)
#define SM_W2  135168                // 32768 (hi only; lo via __ldg)
#define SM_C1  167936                // 32768
#define SM_META 200704               // ~7KB
#define EDGE_SMEM 207872

// ---------------------------------------------------------------- zero
__global__ void zero_kernel(int N) {
    int i = blockIdx.x * blockDim.x + threadIdx.x;
    if (i < N * HD) g_mi[i] = 0.0f;
    int j = i - N * HD;
    if (j >= 0 && j < N * 3) g_psum[j] = 0.0f;
    int k = i - N * (HD + 3);
    if (k >= 0 && k < N) g_cnt[k] = 0.0f;
}

// ---------------------------------------------------------------- weight prep
__global__ void prep_weights_kernel(const float* __restrict__ eW2,
                                    const float* __restrict__ cW1) {
    int i = blockIdx.x * blockDim.x + threadIdx.x;
    if (i >= HD * HD) return;
    int k = i >> 7, n = i & 127;
    unsigned off = (((unsigned)(n >> 3) * 8u + (unsigned)(k >> 4)) * 32u
                    + (unsigned)((n & 7) * 4 + ((k & 7) >> 1))) * 8u
                 + (unsigned)(((k & 15) >> 3) * 4) + (unsigned)((k & 1) * 2);
    __nv_bfloat16 hi, lo;
    bfsplit(eW2[i], hi, lo);
    *(__nv_bfloat16*)(g_imgW2 + off) = hi;
    *(__nv_bfloat16*)(g_imgW2 + 32768 + off) = lo;
    *(__nv_bfloat16*)(g_imgC1 + off) = __float2bfloat16(cW1[i]);
}

// ---------------------------------------------------------------- node pre (R6)
__global__ __launch_bounds__(256) void node_pre_kernel(
    const float* __restrict__ h, const float* __restrict__ eW1, int N)
{
    __shared__ float sH[NTILE * HD];
    const int base = blockIdx.x * NTILE;

    for (int idx = threadIdx.x; idx < NTILE * HD; idx += 256) {
        int n = base + (idx >> 7);
        sH[idx] = (n < N) ? h[(size_t)n * HD + (idx & 127)] : 0.0f;
    }
    __syncthreads();

    const int lane = threadIdx.x & 31;
    const int warp = threadIdx.x >> 5;
    const int jj = lane * 4;
    const int e0 = warp * 8;

    #pragma unroll
    for (int half = 0; half < 2; half++) {
        const float* W = eW1 + (size_t)half * HD * HD;
        float* out = half ? g_Q : g_P;

        float acc[8][4];
        #pragma unroll
        for (int e = 0; e < 8; e++)
            #pragma unroll
            for (int i = 0; i < 4; i++) acc[e][i] = 0.f;

        for (int k = 0; k < HD; k += 4) {
            float4 w0 = *(const float4*)&W[(k + 0) * HD + jj];
            float4 w1 = *(const float4*)&W[(k + 1) * HD + jj];
            float4 w2 = *(const float4*)&W[(k + 2) * HD + jj];
            float4 w3 = *(const float4*)&W[(k + 3) * HD + jj];
            #pragma unroll
            for (int e = 0; e < 8; e++) {
                float4 tv = *(const float4*)&sH[(e0 + e) * HD + k];
                acc[e][0] = fmaf(tv.x, w0.x, acc[e][0]);
                acc[e][1] = fmaf(tv.x, w0.y, acc[e][1]);
                acc[e][2] = fmaf(tv.x, w0.z, acc[e][2]);
                acc[e][3] = fmaf(tv.x, w0.w, acc[e][3]);
                acc[e][0] = fmaf(tv.y, w1.x, acc[e][0]);
                acc[e][1] = fmaf(tv.y, w1.y, acc[e][1]);
                acc[e][2] = fmaf(tv.y, w1.z, acc[e][2]);
                acc[e][3] = fmaf(tv.y, w1.w, acc[e][3]);
                acc[e][0] = fmaf(tv.z, w2.x, acc[e][0]);
                acc[e][1] = fmaf(tv.z, w2.y, acc[e][1]);
                acc[e][2] = fmaf(tv.z, w2.z, acc[e][2]);
                acc[e][3] = fmaf(tv.z, w2.w, acc[e][3]);
                acc[e][0] = fmaf(tv.w, w3.x, acc[e][0]);
                acc[e][1] = fmaf(tv.w, w3.y, acc[e][1]);
                acc[e][2] = fmaf(tv.w, w3.z, acc[e][2]);
                acc[e][3] = fmaf(tv.w, w3.w, acc[e][3]);
            }
        }
        #pragma unroll
        for (int e = 0; e < 8; e++) {
            int n = base + e0 + e;
            if (n < N) {
                float4 o = make_float4(acc[e][0], acc[e][1], acc[e][2], acc[e][3]);
                *(float4*)&out[(size_t)n * HD + jj] = o;
            }
        }
    }
}

// ---------------------------------------------------------------- edge kernel
// Persistent, 512 threads (16 warps), 1 CTA/SM, 256-edge tiles.
// Warp w owns matom w: 16 rows x full 128 cols. GEMM1 C-frags convert to
// GEMM2 A-frags in registers (no SMEM repack).
__global__ __launch_bounds__(512, 1) void edge_kernel(
    const float* __restrict__ pos,
    const int* __restrict__ eidx,
    const float* __restrict__ eW1, const float* __restrict__ eb1,
    const float* __restrict__ eb2,
    const float* __restrict__ cb1, const float* __restrict__ cW2,
    int N, int E, int numTiles)
{
    extern __shared__ __align__(16) unsigned char S[];

    const int tid  = threadIdx.x;
    const int w    = tid >> 5;
    const int lane = tid & 31;

    int*   sR  = (int*)(S + SM_META);
    int*   sC  = (int*)(S + SM_META + 1024);
    float* sSq = (float*)(S + SM_META + 2048);
    float* sDx = (float*)(S + SM_META + 3072);
    float* sDy = (float*)(S + SM_META + 4096);
    float* sDz = (float*)(S + SM_META + 5120);
    float* sPart = (float*)(S + SM_META + 6144);  // [256]

    // stage W2-hi and C1-hi images once
    {
        const uint4* a = (const uint4*)g_imgW2;          // hi half
        const uint4* b = (const uint4*)g_imgC1;
        uint4* wa = (uint4*)(S + SM_W2);
        uint4* wb = (uint4*)(S + SM_C1);
        for (int i = tid; i < 2048; i += 512) { wa[i] = a[i]; wb[i] = b[i]; }
    }

    const float* w256 = eW1 + 256 * HD;

    // gather constants: warp per edge (16 edges/warp), lane = 4 consecutive cols
    const int gk = lane * 4;
    const float4 gW = __ldg((const float4*)&w256[gk]);
    const float4 gB = __ldg((const float4*)&eb1[gk]);
    const unsigned gKstep = (unsigned)(gk >> 4);
    const int gkl = gk & 15;
    const unsigned gLaneD = (unsigned)((gkl & 7) >> 1);
    const unsigned gRegD4 = (unsigned)(((gkl >> 3) << 1) * 4);

    // mma tile mapping: warp w = matom w (16 rows), full 128 cols
    const int rowT = lane >> 2;
    const int colJ = (lane & 3) * 2;

    for (int t = blockIdx.x; t < numTiles; t += gridDim.x) {
        const int base = t * ETILE;
        __syncthreads();   // protect meta/A reuse across tiles

        if (tid < ETILE) {
            int e = base + tid;
            int r = eidx[e];
            int c = eidx[E + e];
            float dx = pos[r * 3 + 0] - pos[c * 3 + 0];
            float dy = pos[r * 3 + 1] - pos[c * 3 + 1];
            float dz = pos[r * 3 + 2] - pos[c * 3 + 2];
            sR[tid] = r; sC[tid] = c;
            sSq[tid] = dx * dx + dy * dy + dz * dz;
            sDx[tid] = dx; sDy[tid] = dy; sDz[tid] = dz;
        }
        __syncthreads();

        // ---- gather: warp per edge (coalesced), silu, split, pack
        #pragma unroll 2
        for (int it = 0; it < 16; it++) {
            int e = w * 16 + it;
            int r = sR[e], c = sC[e];
            float sq = sSq[e];
            float4 P = __ldg((const float4*)&g_P[(size_t)r * HD + gk]);
            float4 Q = __ldg((const float4*)&g_Q[(size_t)c * HD + gk]);
            float v0 = silu(P.x + Q.x + sq * gW.x + gB.x);
            float v1 = silu(P.y + Q.y + sq * gW.y + gB.y);
            float v2 = silu(P.z + Q.z + sq * gW.z + gB.z);
            float v3 = silu(P.w + Q.w + sq * gW.w + gB.w);
            int matom = e >> 4, eloc = e & 15;
            unsigned s0 = ((unsigned)(matom * 8) + gKstep) * ABLK
                        + ((unsigned)((eloc & 7) * 4) + gLaneD) * 16u
                        + (unsigned)((eloc >> 3) * 4) + gRegD4;
            __nv_bfloat16 h0, h1, h2, h3, l0, l1, l2, l3;
            bfsplit(v0, h0, l0); bfsplit(v1, h1, l1);
            bfsplit(v2, h2, l2); bfsplit(v3, h3, l3);
            *(unsigned*)(S + SM_A + s0)            = bfpack(h0, h1);
            *(unsigned*)(S + SM_A + s0 + 16)       = bfpack(h2, h3);
            *(unsigned*)(S + SM_A + ALO + s0)      = bfpack(l0, l1);
            *(unsigned*)(S + SM_A + ALO + s0 + 16) = bfpack(l2, l3);
        }
        __syncthreads();

        // ---- GEMM1: 16x128 per warp, 3 bf16 passes (hi*hi, hi*lo, lo*hi)
        float acc[16][4];
        #pragma unroll
        for (int ni = 0; ni < 16; ni++)
            #pragma unroll
            for (int q = 0; q < 4; q++) acc[ni][q] = 0.f;

        // pass 0: A-hi x B-hi (SMEM) ; pass 1: A-hi x B-lo (global) ;
        // pass 2: A-lo (SMEM) x B-hi (SMEM)
        #pragma unroll
        for (int pass = 0; pass < 3; pass++) {
            unsigned aBase = SM_A + ((pass == 2) ? (unsigned)ALO : 0u);
            #pragma unroll
            for (int ks = 0; ks < 8; ks++) {
                uint4 a0 = *(const uint4*)(S + aBase
                          + (w * 8 + ks) * ABLK + lane * 16);
                #pragma unroll
                for (int nc = 0; nc < 4; nc++) {
                    uint2 bv[4];
                    #pragma unroll
                    for (int nj = 0; nj < 4; nj++) {
                        unsigned boff = (((unsigned)(nc * 4 + nj) * 8u + (unsigned)ks)
                                         * 32u + (unsigned)lane) * 8u;
                        if (pass == 1)
                            bv[nj] = __ldg((const uint2*)(g_imgW2 + 32768 + boff));
                        else
                            bv[nj] = *(const uint2*)(S + SM_W2 + boff);
                    }
                    #pragma unroll
                    for (int nj = 0; nj < 4; nj++)
                        mma_bf16(acc[nc * 4 + nj], a0, bv[nj]);
                }
            }
        }

        // ---- epilogue 1: m = silu(D1 + eb2); scatter; convert C->A frags in regs
        uint4 mf[8];
        {
            int e0r = w * 16 + rowT;
            size_t rb0 = (size_t)sR[e0r] * HD;
            size_t rb1 = (size_t)sR[e0r + 8] * HD;
            #pragma unroll
            for (int ks = 0; ks < 8; ks++) {
                int n0 = 16 * ks + colJ;
                int n1 = n0 + 8;
                float b00 = __ldg(&eb2[n0]), b01 = __ldg(&eb2[n0 + 1]);
                float b10 = __ldg(&eb2[n1]), b11 = __ldg(&eb2[n1 + 1]);
                float m00 = silu(acc[2 * ks][0] + b00);
                float m01 = silu(acc[2 * ks][1] + b01);
                float m02 = silu(acc[2 * ks][2] + b00);
                float m03 = silu(acc[2 * ks][3] + b01);
                float m10 = silu(acc[2 * ks + 1][0] + b10);
                float m11 = silu(acc[2 * ks + 1][1] + b11);
                float m12 = silu(acc[2 * ks + 1][2] + b10);
                float m13 = silu(acc[2 * ks + 1][3] + b11);
                red_add_v2(&g_mi[rb0 + n0], m00, m01);
                red_add_v2(&g_mi[rb1 + n0], m02, m03);
                red_add_v2(&g_mi[rb0 + n1], m10, m11);
                red_add_v2(&g_mi[rb1 + n1], m12, m13);
                // C->A fragment identity (m16n8k16):
                mf[ks].x = bfpackf(m00, m01);   // row rowT,   k = 16ks+colJ..+1
                mf[ks].y = bfpackf(m02, m03);   // row rowT+8
                mf[ks].z = bfpackf(m10, m11);   // row rowT,   k+8
                mf[ks].w = bfpackf(m12, m13);   // row rowT+8, k+8
            }
        }

        // ---- GEMM2: D2 = M @ cW1 (A from registers, single bf16 pass)
        #pragma unroll
        for (int ni = 0; ni < 16; ni++)
            #pragma unroll
            for (int q = 0; q < 4; q++) acc[ni][q] = 0.f;

        #pragma unroll
        for (int ks = 0; ks < 8; ks++) {
            #pragma unroll
            for (int nc = 0; nc < 4; nc++) {
                uint2 bv[4];
                #pragma unroll
                for (int nj = 0; nj < 4; nj++)
                    bv[nj] = *(const uint2*)(S + SM_C1
                             + (((unsigned)(nc * 4 + nj) * 8u + (unsigned)ks)
                                * 32u + (unsigned)lane) * 8u);
                #pragma unroll
                for (int nj = 0; nj < 4; nj++)
                    mma_bf16(acc[nc * 4 + nj], mf[ks], bv[nj]);
            }
        }

        // ---- epilogue 2: cw = silu(D2 + cb1) . cW2 over full 128 cols
        {
            float s0 = 0.f, s1 = 0.f;
            #pragma unroll
            for (int ni = 0; ni < 16; ni++) {
                int n = ni * 8 + colJ;
                float cb0 = __ldg(&cb1[n]),  cb1v = __ldg(&cb1[n + 1]);
                float cw0 = __ldg(&cW2[n]),  cw1v = __ldg(&cW2[n + 1]);
                s0 += silu(acc[ni][0] + cb0) * cw0
                    + silu(acc[ni][1] + cb1v) * cw1v;
                s1 += silu(acc[ni][2] + cb0) * cw0
                    + silu(acc[ni][3] + cb1v) * cw1v;
            }
            s0 += __shfl_xor_sync(0xFFFFFFFFu, s0, 1);
            s0 += __shfl_xor_sync(0xFFFFFFFFu, s0, 2);
            s1 += __shfl_xor_sync(0xFFFFFFFFu, s1, 1);
            s1 += __shfl_xor_sync(0xFFFFFFFFu, s1, 2);
            if ((lane & 3) == 0) {
                int e0r = w * 16 + rowT;
                sPart[e0r]     = s0;
                sPart[e0r + 8] = s1;
            }
        }
        __syncthreads();

        if (tid < ETILE) {
            float cw = sPart[tid];
            float inv = rsqrtf(sSq[tid] + 1e-8f);
            float wgt = cw * inv;
            int r = sR[tid];
            atomicAdd(&g_psum[r * 3 + 0], sDx[tid] * wgt);
            atomicAdd(&g_psum[r * 3 + 1], sDy[tid] * wgt);
            atomicAdd(&g_psum[r * 3 + 2], sDz[tid] * wgt);
            atomicAdd(&g_cnt[r], 1.0f);
        }
    }
}

// ---------------------------------------------------------------- node out (R6, f32x2)
__device__ __forceinline__ void fma2(unsigned long long& acc,
                                     unsigned long long a, unsigned long long b) {
    asm("fma.rn.f32x2 %0, %1, %2, %0;" : "+l"(acc) : "l"(a), "l"(b));
}
__device__ __forceinline__ unsigned long long dup2(float x) {
    unsigned long long r;
    asm("mov.b64 %0, {%1, %1};" : "=l"(r) : "f"(x));
    return r;
}
__device__ __forceinline__ void lds_v2u64(unsigned long long& a, unsigned long long& b,
                                          unsigned addr) {
    asm volatile("ld.shared.v2.b64 {%0, %1}, [%2];" : "=l"(a), "=l"(b) : "r"(addr));
}
__device__ __forceinline__ float f2lo(unsigned long long v) {
    return __uint_as_float((unsigned)(v & 0xFFFFFFFFull));
}
__device__ __forceinline__ float f2hi(unsigned long long v) {
    return __uint_as_float((unsigned)(v >> 32));
}

__global__ __launch_bounds__(128) void node_out_kernel(
    const float* __restrict__ h, const float* __restrict__ pos,
    const float* __restrict__ nW1, const float* __restrict__ nb1,
    const float* __restrict__ nW2, const float* __restrict__ nb2,
    float* __restrict__ outH, float* __restrict__ outP, int N)
{
    __shared__ __align__(16) float2 sXp[16 * 2 * HD];

    const int base = blockIdx.x * 32;
    const int tid = threadIdx.x;

    for (int idx = tid; idx < 16 * (2 * HD / 4); idx += 128) {
        int p = idx >> 6, kg = idx & 63, k = kg << 2;
        int n0 = base + 2 * p, n1 = n0 + 1;
        float4 a, b;
        if (k < HD) {
            a = __ldg((const float4*)&h[(size_t)n0 * HD + k]);
            b = __ldg((const float4*)&h[(size_t)n1 * HD + k]);
        } else {
            a = *(const float4*)&g_mi[(size_t)n0 * HD + (k - HD)];
            b = *(const float4*)&g_mi[(size_t)n1 * HD + (k - HD)];
        }
        *(float4*)&sXp[p * 2 * HD + k]     = make_float4(a.x, b.x, a.y, b.y);
        *(float4*)&sXp[p * 2 * HD + k + 2] = make_float4(a.z, b.z, a.w, b.w);
    }
    __syncthreads();

    const int lane = tid & 31;
    const int warp = tid >> 5;
    const int jj = lane * 4;
    const int p0 = warp * 4;
    const unsigned x0 = smem_u32(sXp) + (unsigned)(p0 * 2 * HD) * 8u;

    {
        unsigned long long acc[4][4];
        #pragma unroll
        for (int p = 0; p < 4; p++)
            #pragma unroll
            for (int c = 0; c < 4; c++) acc[p][c] = 0ull;

        #pragma unroll 2
        for (int kk = 0; kk < 2 * HD; kk += 2) {
            float4 wA = __ldg((const float4*)&nW1[(kk + 0) * HD + jj]);
            float4 wB = __ldg((const float4*)&nW1[(kk + 1) * HD + jj]);
            unsigned long long wa0 = dup2(wA.x), wa1 = dup2(wA.y),
                               wa2 = dup2(wA.z), wa3 = dup2(wA.w);
            unsigned long long wb0 = dup2(wB.x), wb1 = dup2(wB.y),
                               wb2 = dup2(wB.z), wb3 = dup2(wB.w);
            #pragma unroll
            for (int p = 0; p < 4; p++) {
                unsigned long long t0, t1;
                lds_v2u64(t0, t1, x0 + (unsigned)(p * 2 * HD + kk) * 8u);
                fma2(acc[p][0], t0, wa0);
                fma2(acc[p][1], t0, wa1);
                fma2(acc[p][2], t0, wa2);
                fma2(acc[p][3], t0, wa3);
                fma2(acc[p][0], t1, wb0);
                fma2(acc[p][1], t1, wb1);
                fma2(acc[p][2], t1, wb2);
                fma2(acc[p][3], t1, wb3);
            }
        }
        __syncwarp();
        float4 b1 = *(const float4*)&nb1[jj];
        float bv[4] = { b1.x, b1.y, b1.z, b1.w };
        #pragma unroll
        for (int p = 0; p < 4; p++) {
            float4 A = make_float4(silu(f2lo(acc[p][0]) + bv[0]),
                                   silu(f2hi(acc[p][0]) + bv[0]),
                                   silu(f2lo(acc[p][1]) + bv[1]),
                                   silu(f2hi(acc[p][1]) + bv[1]));
            float4 B = make_float4(silu(f2lo(acc[p][2]) + bv[2]),
                                   silu(f2hi(acc[p][2]) + bv[2]),
                                   silu(f2lo(acc[p][3]) + bv[3]),
                                   silu(f2hi(acc[p][3]) + bv[3]));
            *(float4*)&sXp[(p0 + p) * 2 * HD + jj]     = A;
            *(float4*)&sXp[(p0 + p) * 2 * HD + jj + 2] = B;
        }
    }
    __syncwarp();

    {
        unsigned long long acc[4][4];
        #pragma unroll
        for (int p = 0; p < 4; p++)
            #pragma unroll
            for (int c = 0; c < 4; c++) acc[p][c] = 0ull;

        #pragma unroll 2
        for (int kk = 0; kk < HD; kk += 2) {
            float4 wA = __ldg((const float4*)&nW2[(kk + 0) * HD + jj]);
            float4 wB = __ldg((const float4*)&nW2[(kk + 1) * HD + jj]);
            unsigned long long wa0 = dup2(wA.x), wa1 = dup2(wA.y),
                               wa2 = dup2(wA.z), wa3 = dup2(wA.w);
            unsigned long long wb0 = dup2(wB.x), wb1 = dup2(wB.y),
                               wb2 = dup2(wB.z), wb3 = dup2(wB.w);
            #pragma unroll
            for (int p = 0; p < 4; p++) {
                unsigned long long t0, t1;
                lds_v2u64(t0, t1, x0 + (unsigned)(p * 2 * HD + kk) * 8u);
                fma2(acc[p][0], t0, wa0);
                fma2(acc[p][1], t0, wa1);
                fma2(acc[p][2], t0, wa2);
                fma2(acc[p][3], t0, wa3);
                fma2(acc[p][0], t1, wb0);
                fma2(acc[p][1], t1, wb1);
                fma2(acc[p][2], t1, wb2);
                fma2(acc[p][3], t1, wb3);
            }
        }
        float4 b2 = *(const float4*)&nb2[jj];
        #pragma unroll
        for (int p = 0; p < 4; p++) {
            int n0 = base + 2 * (p0 + p), n1 = n0 + 1;
            float4 h0 = __ldg((const float4*)&h[(size_t)n0 * HD + jj]);
            float4 h1 = __ldg((const float4*)&h[(size_t)n1 * HD + jj]);
            float4 o0 = make_float4(h0.x + f2lo(acc[p][0]) + b2.x,
                                    h0.y + f2lo(acc[p][1]) + b2.y,
                                    h0.z + f2lo(acc[p][2]) + b2.z,
                                    h0.w + f2lo(acc[p][3]) + b2.w);
            float4 o1 = make_float4(h1.x + f2hi(acc[p][0]) + b2.x,
                                    h1.y + f2hi(acc[p][1]) + b2.y,
                                    h1.z + f2hi(acc[p][2]) + b2.z,
                                    h1.w + f2hi(acc[p][3]) + b2.w);
            *(float4*)&outH[(size_t)n0 * HD + jj] = o0;
            *(float4*)&outH[(size_t)n1 * HD + jj] = o1;
        }
    }

    if (tid < 32) {
        int n = base + tid;
        float c = fmaxf(g_cnt[n], 1.0f);
        outP[n * 3 + 0] = pos[n * 3 + 0] + g_psum[n * 3 + 0] / c;
        outP[n * 3 + 1] = pos[n * 3 + 1] + g_psum[n * 3 + 1] / c;
        outP[n * 3 + 2] = pos[n * 3 + 2] + g_psum[n * 3 + 2] / c;
    }
}

// ---------------------------------------------------------------- launch
extern "C" void kernel_launch(void* const* d_in, const int* in_sizes, int n_in,
                              void* d_out, int out_size)
{
    const float* h    = (const float*)d_in[0];
    const float* pos  = (const float*)d_in[1];
    const int*   eidx = (const int*)d_in[2];
    const float* eW1  = (const float*)d_in[3];
    const float* eb1  = (const float*)d_in[4];
    const float* eW2  = (const float*)d_in[5];
    const float* eb2  = (const float*)d_in[6];
    const float* cW1  = (const float*)d_in[7];
    const float* cb1  = (const float*)d_in[8];
    const float* cW2  = (const float*)d_in[9];
    const float* nW1  = (const float*)d_in[10];
    const float* nb1  = (const float*)d_in[11];
    const float* nW2  = (const float*)d_in[12];
    const float* nb2  = (const float*)d_in[13];

    const int N = in_sizes[0] / HD;
    const int E = in_sizes[2] / 2;

    float* outH = (float*)d_out;
    float* outP = outH + (size_t)N * HD;

    cudaFuncSetAttribute(edge_kernel, cudaFuncAttributeMaxDynamicSharedMemorySize,
                         EDGE_SMEM);

    zero_kernel<<<(N * (HD + 4) + 255) / 256, 256>>>(N);
    prep_weights_kernel<<<(HD * HD + 255) / 256, 256>>>(eW2, cW1);
    node_pre_kernel<<<(N + NTILE - 1) / NTILE, 256>>>(h, eW1, N);
    edge_kernel<<<152, 512, EDGE_SMEM>>>(pos, eidx, eW1, eb1, eb2, cb1, cW2,
                                         N, E, E / ETILE);
    node_out_kernel<<<N / 32, 128>>>(h, pos, nW1, nb1, nW2, nb2, outH, outP, N);
}

// round 15
// speedup vs baseline: 1.0875x; 1.0875x over previous
#include <cuda_runtime.h>
#include <cuda_bf16.h>
#include <math.h>

#define HD 128
#define ETILE 128
#define NTILE 64
#define NMAX 20000
#define EMAX 640000

// ---------------- scratch (device globals: allocation-free)
__device__ float g_P[NMAX * HD];
__device__ float g_Q[NMAX * HD];
__device__ float g_mi[NMAX * HD];
__device__ float g_psum[NMAX * 3];
__device__ float g_cnt[NMAX];
// paired-fragment transposed weight images (2 n-atoms share a 16B lane slot)
__device__ __align__(16) unsigned char g_imgW2[65536];  // eW2^T bf16 hi(0)/lo(32768)
__device__ __align__(16) unsigned char g_imgC1[32768];  // cW1^T bf16 hi only

// ---------------- helpers
__device__ __forceinline__ float silu(float x) {
    float hx = 0.5f * x;
    float t;
    asm("tanh.approx.f32 %0, %1;" : "=f"(t) : "f"(hx));
    return fmaf(hx, t, hx);
}

__device__ __forceinline__ unsigned smem_u32(const void* p) {
    unsigned r;
    asm("{ .reg .u64 t; cvta.to.shared.u64 t, %1; cvt.u32.u64 %0, t; }"
        : "=r"(r) : "l"(p));
    return r;
}

__device__ __forceinline__ void red_add_v2(float* p, float a, float b) {
    asm volatile("red.global.add.v2.f32 [%0], {%1, %2};"
                 :: "l"(p), "f"(a), "f"(b) : "memory");
}

__device__ __forceinline__ unsigned bfpack(__nv_bfloat16 a, __nv_bfloat16 b) {
    unsigned short ua = __bfloat16_as_ushort(a), ub = __bfloat16_as_ushort(b);
    return (unsigned)ua | ((unsigned)ub << 16);
}

__device__ __forceinline__ void bfsplit(float v, __nv_bfloat16& hi, __nv_bfloat16& lo) {
    hi = __float2bfloat16(v);
    lo = __float2bfloat16(v - __bfloat162float(hi));
}

// m16n8k16 row.col f32.bf16.bf16.f32 — standard PTX, valid on base sm_103
__device__ __forceinline__ void mma_bf16(float* c, const uint4& a, const uint2& b) {
    asm volatile(
        "mma.sync.aligned.m16n8k16.row.col.f32.bf16.bf16.f32 "
        "{%0,%1,%2,%3}, {%4,%5,%6,%7}, {%8,%9}, {%0,%1,%2,%3};"
        : "+f"(c[0]), "+f"(c[1]), "+f"(c[2]), "+f"(c[3])
        : "r"(a.x), "r"(a.y), "r"(a.z), "r"(a.w), "r"(b.x), "r"(b.y));
}

// SMEM layout
#define ABLK   528
#define ALO    33792                 // 8*8*528
#define SM_A   0                     // 67584
#define SM_W2  67584                 // 65536 (hi @0, lo @32768)
#define SM_C1  133120                // 32768
#define SM_META 165888               // ~4KB
#define EDGE_SMEM 169984

// ---------------------------------------------------------------- zero
__global__ void zero_kernel(int N) {
    int i = blockIdx.x * blockDim.x + threadIdx.x;
    if (i < N * HD) g_mi[i] = 0.0f;
    int j = i - N * HD;
    if (j >= 0 && j < N * 3) g_psum[j] = 0.0f;
    int k = i - N * (HD + 3);
    if (k >= 0 && k < N) g_cnt[k] = 0.0f;
}

// ---------------------------------------------------------------- weight prep
// Paired layout: uint4 slot per (npair, kstep, lane); low uint2 = even n-atom,
// high uint2 = odd n-atom.  byte = ((npair*8+ks)*32 + lane)*16
//                                  + ((n>>3)&1)*8 + reg*4 + (k&1)*2
__global__ void prep_weights_kernel(const float* __restrict__ eW2,
                                    const float* __restrict__ cW1) {
    int i = blockIdx.x * blockDim.x + threadIdx.x;
    if (i >= HD * HD) return;
    int k = i >> 7, n = i & 127;
    unsigned lane = (unsigned)((n & 7) * 4 + ((k & 7) >> 1));
    unsigned off = (((unsigned)(n >> 4) * 8u + (unsigned)(k >> 4)) * 32u + lane) * 16u
                 + (unsigned)(((n >> 3) & 1) * 8)
                 + (unsigned)(((k & 15) >> 3) * 4) + (unsigned)((k & 1) * 2);
    __nv_bfloat16 hi, lo;
    bfsplit(eW2[i], hi, lo);
    *(__nv_bfloat16*)(g_imgW2 + off) = hi;
    *(__nv_bfloat16*)(g_imgW2 + 32768 + off) = lo;
    *(__nv_bfloat16*)(g_imgC1 + off) = __float2bfloat16(cW1[i]);
}

// ---------------------------------------------------------------- node pre (R6)
__global__ __launch_bounds__(256) void node_pre_kernel(
    const float* __restrict__ h, const float* __restrict__ eW1, int N)
{
    __shared__ float sH[NTILE * HD];
    const int base = blockIdx.x * NTILE;

    for (int idx = threadIdx.x; idx < NTILE * HD; idx += 256) {
        int n = base + (idx >> 7);
        sH[idx] = (n < N) ? h[(size_t)n * HD + (idx & 127)] : 0.0f;
    }
    __syncthreads();

    const int lane = threadIdx.x & 31;
    const int warp = threadIdx.x >> 5;
    const int jj = lane * 4;
    const int e0 = warp * 8;

    #pragma unroll
    for (int half = 0; half < 2; half++) {
        const float* W = eW1 + (size_t)half * HD * HD;
        float* out = half ? g_Q : g_P;

        float acc[8][4];
        #pragma unroll
        for (int e = 0; e < 8; e++)
            #pragma unroll
            for (int i = 0; i < 4; i++) acc[e][i] = 0.f;

        for (int k = 0; k < HD; k += 4) {
            float4 w0 = *(const float4*)&W[(k + 0) * HD + jj];
            float4 w1 = *(const float4*)&W[(k + 1) * HD + jj];
            float4 w2 = *(const float4*)&W[(k + 2) * HD + jj];
            float4 w3 = *(const float4*)&W[(k + 3) * HD + jj];
            #pragma unroll
            for (int e = 0; e < 8; e++) {
                float4 tv = *(const float4*)&sH[(e0 + e) * HD + k];
                acc[e][0] = fmaf(tv.x, w0.x, acc[e][0]);
                acc[e][1] = fmaf(tv.x, w0.y, acc[e][1]);
                acc[e][2] = fmaf(tv.x, w0.z, acc[e][2]);
                acc[e][3] = fmaf(tv.x, w0.w, acc[e][3]);
                acc[e][0] = fmaf(tv.y, w1.x, acc[e][0]);
                acc[e][1] = fmaf(tv.y, w1.y, acc[e][1]);
                acc[e][2] = fmaf(tv.y, w1.z, acc[e][2]);
                acc[e][3] = fmaf(tv.y, w1.w, acc[e][3]);
                acc[e][0] = fmaf(tv.z, w2.x, acc[e][0]);
                acc[e][1] = fmaf(tv.z, w2.y, acc[e][1]);
                acc[e][2] = fmaf(tv.z, w2.z, acc[e][2]);
                acc[e][3] = fmaf(tv.z, w2.w, acc[e][3]);
                acc[e][0] = fmaf(tv.w, w3.x, acc[e][0]);
                acc[e][1] = fmaf(tv.w, w3.y, acc[e][1]);
                acc[e][2] = fmaf(tv.w, w3.z, acc[e][2]);
                acc[e][3] = fmaf(tv.w, w3.w, acc[e][3]);
            }
        }
        #pragma unroll
        for (int e = 0; e < 8; e++) {
            int n = base + e0 + e;
            if (n < N) {
                float4 o = make_float4(acc[e][0], acc[e][1], acc[e][2], acc[e][3]);
                *(float4*)&out[(size_t)n * HD + jj] = o;
            }
        }
    }
}

// ---------------------------------------------------------------- edge kernel
// Persistent, 512 threads (16 warps), 1 CTA/SM (R13 structure).
// Warp w: matom mA = w&7 (16 rows), col half (w>>3)*64 (4 npairs).
__global__ __launch_bounds__(512, 1) void edge_kernel(
    const float* __restrict__ pos,
    const int* __restrict__ eidx,
    const float* __restrict__ eW1, const float* __restrict__ eb1,
    const float* __restrict__ eb2,
    const float* __restrict__ cb1, const float* __restrict__ cW2,
    int N, int E, int numTiles)
{
    extern __shared__ __align__(16) unsigned char S[];

    const int tid  = threadIdx.x;
    const int w    = tid >> 5;
    const int lane = tid & 31;

    int*   sR  = (int*)(S + SM_META);
    int*   sC  = (int*)(S + SM_META + 512);
    float* sSq = (float*)(S + SM_META + 1024);
    float* sDx = (float*)(S + SM_META + 1536);
    float* sDy = (float*)(S + SM_META + 2048);
    float* sDz = (float*)(S + SM_META + 2560);
    float* sPart = (float*)(S + SM_META + 3072);  // [2][128]

    // stage weight images once
    {
        const uint4* a = (const uint4*)g_imgW2;
        const uint4* b = (const uint4*)g_imgC1;
        uint4* wa = (uint4*)(S + SM_W2);
        uint4* wb = (uint4*)(S + SM_C1);
        for (int i = tid; i < 4096; i += 512) wa[i] = a[i];
        for (int i = tid; i < 2048; i += 512) wb[i] = b[i];
    }

    const float* w256 = eW1 + 256 * HD;

    // gather constants: warp per edge (8 edges/warp), lane = 4 consecutive cols
    const int gk = lane * 4;
    const float4 gW = __ldg((const float4*)&w256[gk]);
    const float4 gB = __ldg((const float4*)&eb1[gk]);
    const unsigned gKstep = (unsigned)(gk >> 4);
    const int gkl = gk & 15;
    const unsigned gLaneD = (unsigned)((gkl & 7) >> 1);
    const unsigned gRegD4 = (unsigned)(((gkl >> 3) << 1) * 4);

    // mma tile mapping
    const int mA = w & 7;              // matom (16 rows)
    const int nh = w >> 3;             // col half
    const int rowT = lane >> 2;
    const int colJ = (lane & 3) * 2;

    for (int t = blockIdx.x; t < numTiles; t += gridDim.x) {
        const int base = t * ETILE;
        __syncthreads();   // protect SMEM reuse across tiles

        if (tid < ETILE) {
            int e = base + tid;
            int r = eidx[e];
            int c = eidx[E + e];
            float dx = pos[r * 3 + 0] - pos[c * 3 + 0];
            float dy = pos[r * 3 + 1] - pos[c * 3 + 1];
            float dz = pos[r * 3 + 2] - pos[c * 3 + 2];
            sR[tid] = r; sC[tid] = c;
            sSq[tid] = dx * dx + dy * dy + dz * dz;
            sDx[tid] = dx; sDy[tid] = dy; sDz[tid] = dz;
        }
        __syncthreads();

        // ---- gather: warp per edge (coalesced), silu, split, pack
        #pragma unroll 2
        for (int it = 0; it < 8; it++) {
            int e = w * 8 + it;
            int r = sR[e], c = sC[e];
            float sq = sSq[e];
            float4 P = __ldg((const float4*)&g_P[(size_t)r * HD + gk]);
            float4 Q = __ldg((const float4*)&g_Q[(size_t)c * HD + gk]);
            float v0 = silu(P.x + Q.x + sq * gW.x + gB.x);
            float v1 = silu(P.y + Q.y + sq * gW.y + gB.y);
            float v2 = silu(P.z + Q.z + sq * gW.z + gB.z);
            float v3 = silu(P.w + Q.w + sq * gW.w + gB.w);
            int matom = e >> 4, eloc = e & 15;
            unsigned s0 = ((unsigned)(matom * 8) + gKstep) * ABLK
                        + ((unsigned)((eloc & 7) * 4) + gLaneD) * 16u
                        + (unsigned)((eloc >> 3) * 4) + gRegD4;
            __nv_bfloat16 h0, h1, h2, h3, l0, l1, l2, l3;
            bfsplit(v0, h0, l0); bfsplit(v1, h1, l1);
            bfsplit(v2, h2, l2); bfsplit(v3, h3, l3);
            *(unsigned*)(S + SM_A + s0)            = bfpack(h0, h1);
            *(unsigned*)(S + SM_A + s0 + 16)       = bfpack(h2, h3);
            *(unsigned*)(S + SM_A + ALO + s0)      = bfpack(l0, l1);
            *(unsigned*)(S + SM_A + ALO + s0 + 16) = bfpack(l2, l3);
        }
        __syncthreads();

        // ---- GEMM1: 16x64 per warp, 3 bf16 passes (hh, h-lo, lo-h)
        float acc[8][4];
        #pragma unroll
        for (int ni = 0; ni < 8; ni++)
            #pragma unroll
            for (int q = 0; q < 4; q++) acc[ni][q] = 0.f;

        #pragma unroll
        for (int pass = 0; pass < 3; pass++) {
            unsigned aBase = SM_A + ((pass == 2) ? (unsigned)ALO : 0u);
            unsigned bBase = SM_W2 + ((pass == 1) ? 32768u : 0u);
            #pragma unroll
            for (int ks = 0; ks < 8; ks++) {
                uint4 a0 = *(const uint4*)(S + aBase
                          + (mA * 8 + ks) * ABLK + lane * 16);
                #pragma unroll
                for (int p = 0; p < 4; p++) {
                    uint4 bq = *(const uint4*)(S + bBase
                              + (((nh * 4 + p) * 8 + ks) * 32 + lane) * 16);
                    uint2 b0 = make_uint2(bq.x, bq.y);
                    uint2 b1 = make_uint2(bq.z, bq.w);
                    mma_bf16(acc[2 * p],     a0, b0);
                    mma_bf16(acc[2 * p + 1], a0, b1);
                }
            }
        }

        // ---- epilogue 1: m = silu(D1 + eb2); scatter; stash packed bf16
        unsigned stash[8][2];
        {
            int e0r = mA * 16 + rowT;
            size_t rb0 = (size_t)sR[e0r] * HD;
            size_t rb1 = (size_t)sR[e0r + 8] * HD;
            #pragma unroll
            for (int ni = 0; ni < 8; ni++) {
                int n = nh * 64 + ni * 8 + colJ;
                float m00 = silu(acc[ni][0] + __ldg(&eb2[n]));
                float m01 = silu(acc[ni][1] + __ldg(&eb2[n + 1]));
                float m10 = silu(acc[ni][2] + __ldg(&eb2[n]));
                float m11 = silu(acc[ni][3] + __ldg(&eb2[n + 1]));
                red_add_v2(&g_mi[rb0 + n], m00, m01);
                red_add_v2(&g_mi[rb1 + n], m10, m11);
                stash[ni][0] = bfpack(__float2bfloat16(m00), __float2bfloat16(m01));
                stash[ni][1] = bfpack(__float2bfloat16(m10), __float2bfloat16(m11));
            }
        }
        __syncthreads();   // all GEMM1 reads of A image complete

        // repack M into A image for GEMM2
        #pragma unroll
        for (int ni = 0; ni < 8; ni++) {
            unsigned kstepD = (unsigned)(nh * 4 + (ni >> 1));
            unsigned slotB = ((unsigned)(mA * 8) + kstepD) * ABLK
                           + (unsigned)lane * 16u;
            unsigned regLo = (unsigned)((ni & 1) << 1);
            *(unsigned*)(S + SM_A + slotB + regLo * 4u)        = stash[ni][0];
            *(unsigned*)(S + SM_A + slotB + (regLo + 1u) * 4u) = stash[ni][1];
        }
        __syncthreads();

        // ---- GEMM2: D2 = M @ cW1 (single bf16 pass)
        #pragma unroll
        for (int ni = 0; ni < 8; ni++)
            #pragma unroll
            for (int q = 0; q < 4; q++) acc[ni][q] = 0.f;

        #pragma unroll
        for (int ks = 0; ks < 8; ks++) {
            uint4 a0 = *(const uint4*)(S + SM_A
                      + (mA * 8 + ks) * ABLK + lane * 16);
            #pragma unroll
            for (int p = 0; p < 4; p++) {
                uint4 bq = *(const uint4*)(S + SM_C1
                          + (((nh * 4 + p) * 8 + ks) * 32 + lane) * 16);
                uint2 b0 = make_uint2(bq.x, bq.y);
                uint2 b1 = make_uint2(bq.z, bq.w);
                mma_bf16(acc[2 * p],     a0, b0);
                mma_bf16(acc[2 * p + 1], a0, b1);
            }
        }

        // ---- epilogue 2: cw partial = silu(D2 + cb1) . cW2
        {
            float s0 = 0.f, s1 = 0.f;
            #pragma unroll
            for (int ni = 0; ni < 8; ni++) {
                int n = nh * 64 + ni * 8 + colJ;
                float cb0 = __ldg(&cb1[n]),  cb1v = __ldg(&cb1[n + 1]);
                float cw0 = __ldg(&cW2[n]),  cw1v = __ldg(&cW2[n + 1]);
                s0 += silu(acc[ni][0] + cb0) * cw0
                    + silu(acc[ni][1] + cb1v) * cw1v;
                s1 += silu(acc[ni][2] + cb0) * cw0
                    + silu(acc[ni][3] + cb1v) * cw1v;
            }
            s0 += __shfl_xor_sync(0xFFFFFFFFu, s0, 1);
            s0 += __shfl_xor_sync(0xFFFFFFFFu, s0, 2);
            s1 += __shfl_xor_sync(0xFFFFFFFFu, s1, 1);
            s1 += __shfl_xor_sync(0xFFFFFFFFu, s1, 2);
            if ((lane & 3) == 0) {
                int e0r = mA * 16 + rowT;
                sPart[nh * 128 + e0r]     = s0;
                sPart[nh * 128 + e0r + 8] = s1;
            }
        }
        __syncthreads();

        if (tid < ETILE) {
            float cw = sPart[tid] + sPart[128 + tid];
            float inv = rsqrtf(sSq[tid] + 1e-8f);
            float wgt = cw * inv;
            int r = sR[tid];
            atomicAdd(&g_psum[r * 3 + 0], sDx[tid] * wgt);
            atomicAdd(&g_psum[r * 3 + 1], sDy[tid] * wgt);
            atomicAdd(&g_psum[r * 3 + 2], sDz[tid] * wgt);
            atomicAdd(&g_cnt[r], 1.0f);
        }
    }
}

// ---------------------------------------------------------------- node out (R6, f32x2)
__device__ __forceinline__ void fma2(unsigned long long& acc,
                                     unsigned long long a, unsigned long long b) {
    asm("fma.rn.f32x2 %0, %1, %2, %0;" : "+l"(acc) : "l"(a), "l"(b));
}
__device__ __forceinline__ unsigned long long dup2(float x) {
    unsigned long long r;
    asm("mov.b64 %0, {%1, %1};" : "=l"(r) : "f"(x));
    return r;
}
__device__ __forceinline__ void lds_v2u64(unsigned long long& a, unsigned long long& b,
                                          unsigned addr) {
    asm volatile("ld.shared.v2.b64 {%0, %1}, [%2];" : "=l"(a), "=l"(b) : "r"(addr));
}
__device__ __forceinline__ float f2lo(unsigned long long v) {
    return __uint_as_float((unsigned)(v & 0xFFFFFFFFull));
}
__device__ __forceinline__ float f2hi(unsigned long long v) {
    return __uint_as_float((unsigned)(v >> 32));
}

__global__ __launch_bounds__(128) void node_out_kernel(
    const float* __restrict__ h, const float* __restrict__ pos,
    const float* __restrict__ nW1, const float* __restrict__ nb1,
    const float* __restrict__ nW2, const float* __restrict__ nb2,
    float* __restrict__ outH, float* __restrict__ outP, int N)
{
    __shared__ __align__(16) float2 sXp[16 * 2 * HD];

    const int base = blockIdx.x * 32;
    const int tid = threadIdx.x;

    for (int idx = tid; idx < 16 * (2 * HD / 4); idx += 128) {
        int p = idx >> 6, kg = idx & 63, k = kg << 2;
        int n0 = base + 2 * p, n1 = n0 + 1;
        float4 a, b;
        if (k < HD) {
            a = __ldg((const float4*)&h[(size_t)n0 * HD + k]);
            b = __ldg((const float4*)&h[(size_t)n1 * HD + k]);
        } else {
            a = *(const float4*)&g_mi[(size_t)n0 * HD + (k - HD)];
            b = *(const float4*)&g_mi[(size_t)n1 * HD + (k - HD)];
        }
        *(float4*)&sXp[p * 2 * HD + k]     = make_float4(a.x, b.x, a.y, b.y);
        *(float4*)&sXp[p * 2 * HD + k + 2] = make_float4(a.z, b.z, a.w, b.w);
    }
    __syncthreads();

    const int lane = tid & 31;
    const int warp = tid >> 5;
    const int jj = lane * 4;
    const int p0 = warp * 4;
    const unsigned x0 = smem_u32(sXp) + (unsigned)(p0 * 2 * HD) * 8u;

    {
        unsigned long long acc[4][4];
        #pragma unroll
        for (int p = 0; p < 4; p++)
            #pragma unroll
            for (int c = 0; c < 4; c++) acc[p][c] = 0ull;

        #pragma unroll 2
        for (int kk = 0; kk < 2 * HD; kk += 2) {
            float4 wA = __ldg((const float4*)&nW1[(kk + 0) * HD + jj]);
            float4 wB = __ldg((const float4*)&nW1[(kk + 1) * HD + jj]);
            unsigned long long wa0 = dup2(wA.x), wa1 = dup2(wA.y),
                               wa2 = dup2(wA.z), wa3 = dup2(wA.w);
            unsigned long long wb0 = dup2(wB.x), wb1 = dup2(wB.y),
                               wb2 = dup2(wB.z), wb3 = dup2(wB.w);
            #pragma unroll
            for (int p = 0; p < 4; p++) {
                unsigned long long t0, t1;
                lds_v2u64(t0, t1, x0 + (unsigned)(p * 2 * HD + kk) * 8u);
                fma2(acc[p][0], t0, wa0);
                fma2(acc[p][1], t0, wa1);
                fma2(acc[p][2], t0, wa2);
                fma2(acc[p][3], t0, wa3);
                fma2(acc[p][0], t1, wb0);
                fma2(acc[p][1], t1, wb1);
                fma2(acc[p][2], t1, wb2);
                fma2(acc[p][3], t1, wb3);
            }
        }
        __syncwarp();
        float4 b1 = *(const float4*)&nb1[jj];
        float bv[4] = { b1.x, b1.y, b1.z, b1.w };
        #pragma unroll
        for (int p = 0; p < 4; p++) {
            float4 A = make_float4(silu(f2lo(acc[p][0]) + bv[0]),
                                   silu(f2hi(acc[p][0]) + bv[0]),
                                   silu(f2lo(acc[p][1]) + bv[1]),
                                   silu(f2hi(acc[p][1]) + bv[1]));
            float4 B = make_float4(silu(f2lo(acc[p][2]) + bv[2]),
                                   silu(f2hi(acc[p][2]) + bv[2]),
                                   silu(f2lo(acc[p][3]) + bv[3]),
                                   silu(f2hi(acc[p][3]) + bv[3]));
            *(float4*)&sXp[(p0 + p) * 2 * HD + jj]     = A;
            *(float4*)&sXp[(p0 + p) * 2 * HD + jj + 2] = B;
        }
    }
    __syncwarp();

    {
        unsigned long long acc[4][4];
        #pragma unroll
        for (int p = 0; p < 4; p++)
            #pragma unroll
            for (int c = 0; c < 4; c++) acc[p][c] = 0ull;

        #pragma unroll 2
        for (int kk = 0; kk < HD; kk += 2) {
            float4 wA = __ldg((const float4*)&nW2[(kk + 0) * HD + jj]);
            float4 wB = __ldg((const float4*)&nW2[(kk + 1) * HD + jj]);
            unsigned long long wa0 = dup2(wA.x), wa1 = dup2(wA.y),
                               wa2 = dup2(wA.z), wa3 = dup2(wA.w);
            unsigned long long wb0 = dup2(wB.x), wb1 = dup2(wB.y),
                               wb2 = dup2(wB.z), wb3 = dup2(wB.w);
            #pragma unroll
            for (int p = 0; p < 4; p++) {
                unsigned long long t0, t1;
                lds_v2u64(t0, t1, x0 + (unsigned)(p * 2 * HD + kk) * 8u);
                fma2(acc[p][0], t0, wa0);
                fma2(acc[p][1], t0, wa1);
                fma2(acc[p][2], t0, wa2);
                fma2(acc[p][3], t0, wa3);
                fma2(acc[p][0], t1, wb0);
                fma2(acc[p][1], t1, wb1);
                fma2(acc[p][2], t1, wb2);
                fma2(acc[p][3], t1, wb3);
            }
        }
        float4 b2 = *(const float4*)&nb2[jj];
        #pragma unroll
        for (int p = 0; p < 4; p++) {
            int n0 = base + 2 * (p0 + p), n1 = n0 + 1;
            float4 h0 = __ldg((const float4*)&h[(size_t)n0 * HD + jj]);
            float4 h1 = __ldg((const float4*)&h[(size_t)n1 * HD + jj]);
            float4 o0 = make_float4(h0.x + f2lo(acc[p][0]) + b2.x,
                                    h0.y + f2lo(acc[p][1]) + b2.y,
                                    h0.z + f2lo(acc[p][2]) + b2.z,
                                    h0.w + f2lo(acc[p][3]) + b2.w);
            float4 o1 = make_float4(h1.x + f2hi(acc[p][0]) + b2.x,
                                    h1.y + f2hi(acc[p][1]) + b2.y,
                                    h1.z + f2hi(acc[p][2]) + b2.z,
                                    h1.w + f2hi(acc[p][3]) + b2.w);
            *(float4*)&outH[(size_t)n0 * HD + jj] = o0;
            *(float4*)&outH[(size_t)n1 * HD + jj] = o1;
        }
    }

    if (tid < 32) {
        int n = base + tid;
        float c = fmaxf(g_cnt[n], 1.0f);
        outP[n * 3 + 0] = pos[n * 3 + 0] + g_psum[n * 3 + 0] / c;
        outP[n * 3 + 1] = pos[n * 3 + 1] + g_psum[n * 3 + 1] / c;
        outP[n * 3 + 2] = pos[n * 3 + 2] + g_psum[n * 3 + 2] / c;
    }
}

// ---------------------------------------------------------------- launch
extern "C" void kernel_launch(void* const* d_in, const int* in_sizes, int n_in,
                              void* d_out, int out_size)
{
    const float* h    = (const float*)d_in[0];
    const float* pos  = (const float*)d_in[1];
    const int*   eidx = (const int*)d_in[2];
    const float* eW1  = (const float*)d_in[3];
    const float* eb1  = (const float*)d_in[4];
    const float* eW2  = (const float*)d_in[5];
    const float* eb2  = (const float*)d_in[6];
    const float* cW1  = (const float*)d_in[7];
    const float* cb1  = (const float*)d_in[8];
    const float* cW2  = (const float*)d_in[9];
    const float* nW1  = (const float*)d_in[10];
    const float* nb1  = (const float*)d_in[11];
    const float* nW2  = (const float*)d_in[12];
    const float* nb2  = (const float*)d_in[13];

    const int N = in_sizes[0] / HD;
    const int E = in_sizes[2] / 2;

    float* outH = (float*)d_out;
    float* outP = outH + (size_t)N * HD;

    cudaFuncSetAttribute(edge_kernel, cudaFuncAttributeMaxDynamicSharedMemorySize,
                         EDGE_SMEM);

    zero_kernel<<<(N * (HD + 4) + 255) / 256, 256>>>(N);
    prep_weights_kernel<<<(HD * HD + 255) / 256, 256>>>(eW2, cW1);
    node_pre_kernel<<<(N + NTILE - 1) / NTILE, 256>>>(h, eW1, N);
    edge_kernel<<<152, 512, EDGE_SMEM>>>(pos, eidx, eW1, eb1, eb2, cb1, cW2,
                                         N, E, E / ETILE);
    node_out_kernel<<<N / 32, 128>>>(h, pos, nW1, nb1, nW2, nb2, outH, outP, N);
}

// round 16
// speedup vs baseline: 1.7722x; 1.6297x over previous
#include <cuda_runtime.h>
#include <cuda_bf16.h>
#include <math.h>

#define HD 128
#define ETILE 128
#define NTILE 64
#define NMAX 20000
#define EMAX 640000

// ---------------- scratch (device globals: allocation-free)
__device__ float g_P[NMAX * HD];
__device__ float g_Q[NMAX * HD];
__device__ float g_mi[NMAX * HD];
__device__ float g_psum[NMAX * 3];
__device__ float g_cnt[NMAX];
// fragment-packed transposed weight images (R13 layout)
__device__ __align__(16) unsigned char g_imgW2[65536];  // eW2^T bf16 hi(0)/lo(32768)
__device__ __align__(16) unsigned char g_imgC1[32768];  // cW1^T bf16 hi only

// ---------------- helpers
__device__ __forceinline__ float silu(float x) {
    float hx = 0.5f * x;
    float t;
    asm("tanh.approx.f32 %0, %1;" : "=f"(t) : "f"(hx));
    return fmaf(hx, t, hx);
}

__device__ __forceinline__ unsigned smem_u32(const void* p) {
    unsigned r;
    asm("{ .reg .u64 t; cvta.to.shared.u64 t, %1; cvt.u32.u64 %0, t; }"
        : "=r"(r) : "l"(p));
    return r;
}

__device__ __forceinline__ void red_add_v2(float* p, float a, float b) {
    asm volatile("red.global.add.v2.f32 [%0], {%1, %2};"
                 :: "l"(p), "f"(a), "f"(b) : "memory");
}

__device__ __forceinline__ unsigned bfpack(__nv_bfloat16 a, __nv_bfloat16 b) {
    unsigned short ua = __bfloat16_as_ushort(a), ub = __bfloat16_as_ushort(b);
    return (unsigned)ua | ((unsigned)ub << 16);
}

__device__ __forceinline__ void bfsplit(float v, __nv_bfloat16& hi, __nv_bfloat16& lo) {
    hi = __float2bfloat16(v);
    lo = __float2bfloat16(v - __bfloat162float(hi));
}

// m16n8k16 row.col f32.bf16.bf16.f32 — standard PTX, valid on base sm_103
__device__ __forceinline__ void mma_bf16(float* c, const uint4& a, const uint2& b) {
    asm volatile(
        "mma.sync.aligned.m16n8k16.row.col.f32.bf16.bf16.f32 "
        "{%0,%1,%2,%3}, {%4,%5,%6,%7}, {%8,%9}, {%0,%1,%2,%3};"
        : "+f"(c[0]), "+f"(c[1]), "+f"(c[2]), "+f"(c[3])
        : "r"(a.x), "r"(a.y), "r"(a.z), "r"(a.w), "r"(b.x), "r"(b.y));
}

// SMEM layout (R13)
#define ABLK   528
#define ALO    33792                 // 8*8*528
#define SM_A   0                     // 67584
#define SM_W2  67584                 // 65536 (hi @0, lo @32768)
#define SM_C1  133120                // 32768
#define SM_META 165888               // ~4KB
#define EDGE_SMEM 169984

// ---------------------------------------------------------------- zero
__global__ void zero_kernel(int N) {
    int i = blockIdx.x * blockDim.x + threadIdx.x;
    if (i < N * HD) g_mi[i] = 0.0f;
    int j = i - N * HD;
    if (j >= 0 && j < N * 3) g_psum[j] = 0.0f;
    int k = i - N * (HD + 3);
    if (k >= 0 && k < N) g_cnt[k] = 0.0f;
}

// ---------------------------------------------------------------- weight prep (R13 layout)
__global__ void prep_weights_kernel(const float* __restrict__ eW2,
                                    const float* __restrict__ cW1) {
    int i = blockIdx.x * blockDim.x + threadIdx.x;
    if (i >= HD * HD) return;
    int k = i >> 7, n = i & 127;
    unsigned off = (((unsigned)(n >> 3) * 8u + (unsigned)(k >> 4)) * 32u
                    + (unsigned)((n & 7) * 4 + ((k & 7) >> 1))) * 8u
                 + (unsigned)(((k & 15) >> 3) * 4) + (unsigned)((k & 1) * 2);
    __nv_bfloat16 hi, lo;
    bfsplit(eW2[i], hi, lo);
    *(__nv_bfloat16*)(g_imgW2 + off) = hi;
    *(__nv_bfloat16*)(g_imgW2 + 32768 + off) = lo;
    *(__nv_bfloat16*)(g_imgC1 + off) = __float2bfloat16(cW1[i]);
}

// ---------------------------------------------------------------- node pre (R6)
__global__ __launch_bounds__(256) void node_pre_kernel(
    const float* __restrict__ h, const float* __restrict__ eW1, int N)
{
    __shared__ float sH[NTILE * HD];
    const int base = blockIdx.x * NTILE;

    for (int idx = threadIdx.x; idx < NTILE * HD; idx += 256) {
        int n = base + (idx >> 7);
        sH[idx] = (n < N) ? h[(size_t)n * HD + (idx & 127)] : 0.0f;
    }
    __syncthreads();

    const int lane = threadIdx.x & 31;
    const int warp = threadIdx.x >> 5;
    const int jj = lane * 4;
    const int e0 = warp * 8;

    #pragma unroll
    for (int half = 0; half < 2; half++) {
        const float* W = eW1 + (size_t)half * HD * HD;
        float* out = half ? g_Q : g_P;

        float acc[8][4];
        #pragma unroll
        for (int e = 0; e < 8; e++)
            #pragma unroll
            for (int i = 0; i < 4; i++) acc[e][i] = 0.f;

        for (int k = 0; k < HD; k += 4) {
            float4 w0 = *(const float4*)&W[(k + 0) * HD + jj];
            float4 w1 = *(const float4*)&W[(k + 1) * HD + jj];
            float4 w2 = *(const float4*)&W[(k + 2) * HD + jj];
            float4 w3 = *(const float4*)&W[(k + 3) * HD + jj];
            #pragma unroll
            for (int e = 0; e < 8; e++) {
                float4 tv = *(const float4*)&sH[(e0 + e) * HD + k];
                acc[e][0] = fmaf(tv.x, w0.x, acc[e][0]);
                acc[e][1] = fmaf(tv.x, w0.y, acc[e][1]);
                acc[e][2] = fmaf(tv.x, w0.z, acc[e][2]);
                acc[e][3] = fmaf(tv.x, w0.w, acc[e][3]);
                acc[e][0] = fmaf(tv.y, w1.x, acc[e][0]);
                acc[e][1] = fmaf(tv.y, w1.y, acc[e][1]);
                acc[e][2] = fmaf(tv.y, w1.z, acc[e][2]);
                acc[e][3] = fmaf(tv.y, w1.w, acc[e][3]);
                acc[e][0] = fmaf(tv.z, w2.x, acc[e][0]);
                acc[e][1] = fmaf(tv.z, w2.y, acc[e][1]);
                acc[e][2] = fmaf(tv.z, w2.z, acc[e][2]);
                acc[e][3] = fmaf(tv.z, w2.w, acc[e][3]);
                acc[e][0] = fmaf(tv.w, w3.x, acc[e][0]);
                acc[e][1] = fmaf(tv.w, w3.y, acc[e][1]);
                acc[e][2] = fmaf(tv.w, w3.z, acc[e][2]);
                acc[e][3] = fmaf(tv.w, w3.w, acc[e][3]);
            }
        }
        #pragma unroll
        for (int e = 0; e < 8; e++) {
            int n = base + e0 + e;
            if (n < N) {
                float4 o = make_float4(acc[e][0], acc[e][1], acc[e][2], acc[e][3]);
                *(float4*)&out[(size_t)n * HD + jj] = o;
            }
        }
    }
}

// ---------------------------------------------------------------- edge kernel (R13 + unroll-4 gather)
// Persistent, 512 threads (16 warps), 1 CTA/SM.
// Warp w: matom mA = w&7 (16 rows), col half (w>>3)*64.
__global__ __launch_bounds__(512, 1) void edge_kernel(
    const float* __restrict__ pos,
    const int* __restrict__ eidx,
    const float* __restrict__ eW1, const float* __restrict__ eb1,
    const float* __restrict__ eb2,
    const float* __restrict__ cb1, const float* __restrict__ cW2,
    int N, int E, int numTiles)
{
    extern __shared__ __align__(16) unsigned char S[];

    const int tid  = threadIdx.x;
    const int w    = tid >> 5;
    const int lane = tid & 31;

    int*   sR  = (int*)(S + SM_META);
    int*   sC  = (int*)(S + SM_META + 512);
    float* sSq = (float*)(S + SM_META + 1024);
    float* sDx = (float*)(S + SM_META + 1536);
    float* sDy = (float*)(S + SM_META + 2048);
    float* sDz = (float*)(S + SM_META + 2560);
    float* sPart = (float*)(S + SM_META + 3072);  // [2][128]

    // stage weight images once
    {
        const uint4* a = (const uint4*)g_imgW2;
        const uint4* b = (const uint4*)g_imgC1;
        uint4* wa = (uint4*)(S + SM_W2);
        uint4* wb = (uint4*)(S + SM_C1);
        for (int i = tid; i < 4096; i += 512) wa[i] = a[i];
        for (int i = tid; i < 2048; i += 512) wb[i] = b[i];
    }

    const float* w256 = eW1 + 256 * HD;

    // gather constants: warp per edge (8 edges/warp), lane = 4 consecutive cols
    const int gk = lane * 4;
    const float4 gW = __ldg((const float4*)&w256[gk]);
    const float4 gB = __ldg((const float4*)&eb1[gk]);
    const unsigned gKstep = (unsigned)(gk >> 4);
    const int gkl = gk & 15;
    const unsigned gLaneD = (unsigned)((gkl & 7) >> 1);
    const unsigned gRegD4 = (unsigned)(((gkl >> 3) << 1) * 4);

    // mma tile mapping
    const int mA = w & 7;              // matom (16 rows)
    const int nh = w >> 3;             // col half
    const int nA0 = nh * 8;            // first natom
    const int rowT = lane >> 2;
    const int colJ = (lane & 3) * 2;

    for (int t = blockIdx.x; t < numTiles; t += gridDim.x) {
        const int base = t * ETILE;
        __syncthreads();   // protect SMEM reuse across tiles

        if (tid < ETILE) {
            int e = base + tid;
            int r = eidx[e];
            int c = eidx[E + e];
            float dx = pos[r * 3 + 0] - pos[c * 3 + 0];
            float dy = pos[r * 3 + 1] - pos[c * 3 + 1];
            float dz = pos[r * 3 + 2] - pos[c * 3 + 2];
            sR[tid] = r; sC[tid] = c;
            sSq[tid] = dx * dx + dy * dy + dz * dz;
            sDx[tid] = dx; sDy[tid] = dy; sDz[tid] = dz;
        }
        __syncthreads();

        // ---- gather: warp per edge (coalesced), silu, split, pack
        // unroll 4 -> 8 P/Q LDG.128 in flight per thread (double R13's MLP)
        #pragma unroll 4
        for (int it = 0; it < 8; it++) {
            int e = w * 8 + it;
            int r = sR[e], c = sC[e];
            float sq = sSq[e];
            float4 P = __ldg((const float4*)&g_P[(size_t)r * HD + gk]);
            float4 Q = __ldg((const float4*)&g_Q[(size_t)c * HD + gk]);
            float v0 = silu(P.x + Q.x + sq * gW.x + gB.x);
            float v1 = silu(P.y + Q.y + sq * gW.y + gB.y);
            float v2 = silu(P.z + Q.z + sq * gW.z + gB.z);
            float v3 = silu(P.w + Q.w + sq * gW.w + gB.w);
            int matom = e >> 4, eloc = e & 15;
            unsigned s0 = ((unsigned)(matom * 8) + gKstep) * ABLK
                        + ((unsigned)((eloc & 7) * 4) + gLaneD) * 16u
                        + (unsigned)((eloc >> 3) * 4) + gRegD4;
            __nv_bfloat16 h0, h1, h2, h3, l0, l1, l2, l3;
            bfsplit(v0, h0, l0); bfsplit(v1, h1, l1);
            bfsplit(v2, h2, l2); bfsplit(v3, h3, l3);
            *(unsigned*)(S + SM_A + s0)            = bfpack(h0, h1);
            *(unsigned*)(S + SM_A + s0 + 16)       = bfpack(h2, h3);
            *(unsigned*)(S + SM_A + ALO + s0)      = bfpack(l0, l1);
            *(unsigned*)(S + SM_A + ALO + s0 + 16) = bfpack(l2, l3);
        }
        __syncthreads();

        // ---- GEMM1: 16x64 per warp, 3 bf16 passes (hh, h-lo, lo-h)
        float acc[8][4];
        #pragma unroll
        for (int ni = 0; ni < 8; ni++)
            #pragma unroll
            for (int q = 0; q < 4; q++) acc[ni][q] = 0.f;

        #pragma unroll
        for (int pass = 0; pass < 3; pass++) {
            unsigned aBase = SM_A + ((pass == 2) ? (unsigned)ALO : 0u);
            unsigned bBase = SM_W2 + ((pass == 1) ? 32768u : 0u);
            #pragma unroll
            for (int ks = 0; ks < 8; ks++) {
                uint4 a0 = *(const uint4*)(S + aBase
                          + (mA * 8 + ks) * ABLK + lane * 16);
                uint2 bv[8];
                #pragma unroll
                for (int ni = 0; ni < 8; ni++)
                    bv[ni] = *(const uint2*)(S + bBase
                             + (((nA0 + ni) * 8 + ks) * 32 + lane) * 8);
                #pragma unroll
                for (int ni = 0; ni < 8; ni++)
                    mma_bf16(acc[ni], a0, bv[ni]);
            }
        }

        // ---- epilogue 1: m = silu(D1 + eb2); scatter; stash packed bf16
        unsigned stash[8][2];
        {
            int e0r = mA * 16 + rowT;
            size_t rb0 = (size_t)sR[e0r] * HD;
            size_t rb1 = (size_t)sR[e0r + 8] * HD;
            #pragma unroll
            for (int ni = 0; ni < 8; ni++) {
                int n = nh * 64 + ni * 8 + colJ;
                float m00 = silu(acc[ni][0] + __ldg(&eb2[n]));
                float m01 = silu(acc[ni][1] + __ldg(&eb2[n + 1]));
                float m10 = silu(acc[ni][2] + __ldg(&eb2[n]));
                float m11 = silu(acc[ni][3] + __ldg(&eb2[n + 1]));
                red_add_v2(&g_mi[rb0 + n], m00, m01);
                red_add_v2(&g_mi[rb1 + n], m10, m11);
                stash[ni][0] = bfpack(__float2bfloat16(m00), __float2bfloat16(m01));
                stash[ni][1] = bfpack(__float2bfloat16(m10), __float2bfloat16(m11));
            }
        }
        __syncthreads();   // all GEMM1 reads of A image complete

        // repack M into A image for GEMM2
        #pragma unroll
        for (int ni = 0; ni < 8; ni++) {
            unsigned kstepD = (unsigned)(nh * 4 + (ni >> 1));
            unsigned slotB = ((unsigned)(mA * 8) + kstepD) * ABLK
                           + (unsigned)lane * 16u;
            unsigned regLo = (unsigned)((ni & 1) << 1);
            *(unsigned*)(S + SM_A + slotB + regLo * 4u)        = stash[ni][0];
            *(unsigned*)(S + SM_A + slotB + (regLo + 1u) * 4u) = stash[ni][1];
        }
        __syncthreads();

        // ---- GEMM2: D2 = M @ cW1 (single bf16 pass)
        #pragma unroll
        for (int ni = 0; ni < 8; ni++)
            #pragma unroll
            for (int q = 0; q < 4; q++) acc[ni][q] = 0.f;

        #pragma unroll
        for (int ks = 0; ks < 8; ks++) {
            uint4 a0 = *(const uint4*)(S + SM_A
                      + (mA * 8 + ks) * ABLK + lane * 16);
            uint2 bv[8];
            #pragma unroll
            for (int ni = 0; ni < 8; ni++)
                bv[ni] = *(const uint2*)(S + SM_C1
                         + (((nA0 + ni) * 8 + ks) * 32 + lane) * 8);
            #pragma unroll
            for (int ni = 0; ni < 8; ni++)
                mma_bf16(acc[ni], a0, bv[ni]);
        }

        // ---- epilogue 2: cw partial = silu(D2 + cb1) . cW2
        {
            float s0 = 0.f, s1 = 0.f;
            #pragma unroll
            for (int ni = 0; ni < 8; ni++) {
                int n = nh * 64 + ni * 8 + colJ;
                float cb0 = __ldg(&cb1[n]),  cb1v = __ldg(&cb1[n + 1]);
                float cw0 = __ldg(&cW2[n]),  cw1v = __ldg(&cW2[n + 1]);
                s0 += silu(acc[ni][0] + cb0) * cw0
                    + silu(acc[ni][1] + cb1v) * cw1v;
                s1 += silu(acc[ni][2] + cb0) * cw0
                    + silu(acc[ni][3] + cb1v) * cw1v;
            }
            s0 += __shfl_xor_sync(0xFFFFFFFFu, s0, 1);
            s0 += __shfl_xor_sync(0xFFFFFFFFu, s0, 2);
            s1 += __shfl_xor_sync(0xFFFFFFFFu, s1, 1);
            s1 += __shfl_xor_sync(0xFFFFFFFFu, s1, 2);
            if ((lane & 3) == 0) {
                int e0r = mA * 16 + rowT;
                sPart[nh * 128 + e0r]     = s0;
                sPart[nh * 128 + e0r + 8] = s1;
            }
        }
        __syncthreads();

        if (tid < ETILE) {
            float cw = sPart[tid] + sPart[128 + tid];
            float inv = rsqrtf(sSq[tid] + 1e-8f);
            float wgt = cw * inv;
            int r = sR[tid];
            atomicAdd(&g_psum[r * 3 + 0], sDx[tid] * wgt);
            atomicAdd(&g_psum[r * 3 + 1], sDy[tid] * wgt);
            atomicAdd(&g_psum[r * 3 + 2], sDz[tid] * wgt);
            atomicAdd(&g_cnt[r], 1.0f);
        }
    }
}

// ---------------------------------------------------------------- node out (R6, f32x2)
__device__ __forceinline__ void fma2(unsigned long long& acc,
                                     unsigned long long a, unsigned long long b) {
    asm("fma.rn.f32x2 %0, %1, %2, %0;" : "+l"(acc) : "l"(a), "l"(b));
}
__device__ __forceinline__ unsigned long long dup2(float x) {
    unsigned long long r;
    asm("mov.b64 %0, {%1, %1};" : "=l"(r) : "f"(x));
    return r;
}
__device__ __forceinline__ void lds_v2u64(unsigned long long& a, unsigned long long& b,
                                          unsigned addr) {
    asm volatile("ld.shared.v2.b64 {%0, %1}, [%2];" : "=l"(a), "=l"(b) : "r"(addr));
}
__device__ __forceinline__ float f2lo(unsigned long long v) {
    return __uint_as_float((unsigned)(v & 0xFFFFFFFFull));
}
__device__ __forceinline__ float f2hi(unsigned long long v) {
    return __uint_as_float((unsigned)(v >> 32));
}

__global__ __launch_bounds__(128) void node_out_kernel(
    const float* __restrict__ h, const float* __restrict__ pos,
    const float* __restrict__ nW1, const float* __restrict__ nb1,
    const float* __restrict__ nW2, const float* __restrict__ nb2,
    float* __restrict__ outH, float* __restrict__ outP, int N)
{
    __shared__ __align__(16) float2 sXp[16 * 2 * HD];

    const int base = blockIdx.x * 32;
    const int tid = threadIdx.x;

    for (int idx = tid; idx < 16 * (2 * HD / 4); idx += 128) {
        int p = idx >> 6, kg = idx & 63, k = kg << 2;
        int n0 = base + 2 * p, n1 = n0 + 1;
        float4 a, b;
        if (k < HD) {
            a = __ldg((const float4*)&h[(size_t)n0 * HD + k]);
            b = __ldg((const float4*)&h[(size_t)n1 * HD + k]);
        } else {
            a = *(const float4*)&g_mi[(size_t)n0 * HD + (k - HD)];
            b = *(const float4*)&g_mi[(size_t)n1 * HD + (k - HD)];
        }
        *(float4*)&sXp[p * 2 * HD + k]     = make_float4(a.x, b.x, a.y, b.y);
        *(float4*)&sXp[p * 2 * HD + k + 2] = make_float4(a.z, b.z, a.w, b.w);
    }
    __syncthreads();

    const int lane = tid & 31;
    const int warp = tid >> 5;
    const int jj = lane * 4;
    const int p0 = warp * 4;
    const unsigned x0 = smem_u32(sXp) + (unsigned)(p0 * 2 * HD) * 8u;

    {
        unsigned long long acc[4][4];
        #pragma unroll
        for (int p = 0; p < 4; p++)
            #pragma unroll
            for (int c = 0; c < 4; c++) acc[p][c] = 0ull;

        #pragma unroll 2
        for (int kk = 0; kk < 2 * HD; kk += 2) {
            float4 wA = __ldg((const float4*)&nW1[(kk + 0) * HD + jj]);
            float4 wB = __ldg((const float4*)&nW1[(kk + 1) * HD + jj]);
            unsigned long long wa0 = dup2(wA.x), wa1 = dup2(wA.y),
                               wa2 = dup2(wA.z), wa3 = dup2(wA.w);
            unsigned long long wb0 = dup2(wB.x), wb1 = dup2(wB.y),
                               wb2 = dup2(wB.z), wb3 = dup2(wB.w);
            #pragma unroll
            for (int p = 0; p < 4; p++) {
                unsigned long long t0, t1;
                lds_v2u64(t0, t1, x0 + (unsigned)(p * 2 * HD + kk) * 8u);
                fma2(acc[p][0], t0, wa0);
                fma2(acc[p][1], t0, wa1);
                fma2(acc[p][2], t0, wa2);
                fma2(acc[p][3], t0, wa3);
                fma2(acc[p][0], t1, wb0);
                fma2(acc[p][1], t1, wb1);
                fma2(acc[p][2], t1, wb2);
                fma2(acc[p][3], t1, wb3);
            }
        }
        __syncwarp();
        float4 b1 = *(const float4*)&nb1[jj];
        float bv[4] = { b1.x, b1.y, b1.z, b1.w };
        #pragma unroll
        for (int p = 0; p < 4; p++) {
            float4 A = make_float4(silu(f2lo(acc[p][0]) + bv[0]),
                                   silu(f2hi(acc[p][0]) + bv[0]),
                                   silu(f2lo(acc[p][1]) + bv[1]),
                                   silu(f2hi(acc[p][1]) + bv[1]));
            float4 B = make_float4(silu(f2lo(acc[p][2]) + bv[2]),
                                   silu(f2hi(acc[p][2]) + bv[2]),
                                   silu(f2lo(acc[p][3]) + bv[3]),
                                   silu(f2hi(acc[p][3]) + bv[3]));
            *(float4*)&sXp[(p0 + p) * 2 * HD + jj]     = A;
            *(float4*)&sXp[(p0 + p) * 2 * HD + jj + 2] = B;
        }
    }
    __syncwarp();

    {
        unsigned long long acc[4][4];
        #pragma unroll
        for (int p = 0; p < 4; p++)
            #pragma unroll
            for (int c = 0; c < 4; c++) acc[p][c] = 0ull;

        #pragma unroll 2
        for (int kk = 0; kk < HD; kk += 2) {
            float4 wA = __ldg((const float4*)&nW2[(kk + 0) * HD + jj]);
            float4 wB = __ldg((const float4*)&nW2[(kk + 1) * HD + jj]);
            unsigned long long wa0 = dup2(wA.x), wa1 = dup2(wA.y),
                               wa2 = dup2(wA.z), wa3 = dup2(wA.w);
            unsigned long long wb0 = dup2(wB.x), wb1 = dup2(wB.y),
                               wb2 = dup2(wB.z), wb3 = dup2(wB.w);
            #pragma unroll
            for (int p = 0; p < 4; p++) {
                unsigned long long t0, t1;
                lds_v2u64(t0, t1, x0 + (unsigned)(p * 2 * HD + kk) * 8u);
                fma2(acc[p][0], t0, wa0);
                fma2(acc[p][1], t0, wa1);
                fma2(acc[p][2], t0, wa2);
                fma2(acc[p][3], t0, wa3);
                fma2(acc[p][0], t1, wb0);
                fma2(acc[p][1], t1, wb1);
                fma2(acc[p][2], t1, wb2);
                fma2(acc[p][3], t1, wb3);
            }
        }
        float4 b2 = *(const float4*)&nb2[jj];
        #pragma unroll
        for (int p = 0; p < 4; p++) {
            int n0 = base + 2 * (p0 + p), n1 = n0 + 1;
            float4 h0 = __ldg((const float4*)&h[(size_t)n0 * HD + jj]);
            float4 h1 = __ldg((const float4*)&h[(size_t)n1 * HD + jj]);
            float4 o0 = make_float4(h0.x + f2lo(acc[p][0]) + b2.x,
                                    h0.y + f2lo(acc[p][1]) + b2.y,
                                    h0.z + f2lo(acc[p][2]) + b2.z,
                                    h0.w + f2lo(acc[p][3]) + b2.w);
            float4 o1 = make_float4(h1.x + f2hi(acc[p][0]) + b2.x,
                                    h1.y + f2hi(acc[p][1]) + b2.y,
                                    h1.z + f2hi(acc[p][2]) + b2.z,
                                    h1.w + f2hi(acc[p][3]) + b2.w);
            *(float4*)&outH[(size_t)n0 * HD + jj] = o0;
            *(float4*)&outH[(size_t)n1 * HD + jj] = o1;
        }
    }

    if (tid < 32) {
        int n = base + tid;
        float c = fmaxf(g_cnt[n], 1.0f);
        outP[n * 3 + 0] = pos[n * 3 + 0] + g_psum[n * 3 + 0] / c;
        outP[n * 3 + 1] = pos[n * 3 + 1] + g_psum[n * 3 + 1] / c;
        outP[n * 3 + 2] = pos[n * 3 + 2] + g_psum[n * 3 + 2] / c;
    }
}

// ---------------------------------------------------------------- launch
extern "C" void kernel_launch(void* const* d_in, const int* in_sizes, int n_in,
                              void* d_out, int out_size)
{
    const float* h    = (const float*)d_in[0];
    const float* pos  = (const float*)d_in[1];
    const int*   eidx = (const int*)d_in[2];
    const float* eW1  = (const float*)d_in[3];
    const float* eb1  = (const float*)d_in[4];
    const float* eW2  = (const float*)d_in[5];
    const float* eb2  = (const float*)d_in[6];
    const float* cW1  = (const float*)d_in[7];
    const float* cb1  = (const float*)d_in[8];
    const float* cW2  = (const float*)d_in[9];
    const float* nW1  = (const float*)d_in[10];
    const float* nb1  = (const float*)d_in[11];
    const float* nW2  = (const float*)d_in[12];
    const float* nb2  = (const float*)d_in[13];

    const int N = in_sizes[0] / HD;
    const int E = in_sizes[2] / 2;

    float* outH = (float*)d_out;
    float* outP = outH + (size_t)N * HD;

    cudaFuncSetAttribute(edge_kernel, cudaFuncAttributeMaxDynamicSharedMemorySize,
                         EDGE_SMEM);

    zero_kernel<<<(N * (HD + 4) + 255) / 256, 256>>>(N);
    prep_weights_kernel<<<(HD * HD + 255) / 256, 256>>>(eW2, cW1);
    node_pre_kernel<<<(N + NTILE - 1) / NTILE, 256>>>(h, eW1, N);
    edge_kernel<<<152, 512, EDGE_SMEM>>>(pos, eidx, eW1, eb1, eb2, cb1, cW2,
                                         N, E, E / ETILE);
    node_out_kernel<<<N / 32, 128>>>(h, pos, nW1, nb1, nW2, nb2, outH, outP, N);
}

// round 17
// speedup vs baseline: 2.0292x; 1.1450x over previous
#include <cuda_runtime.h>
#include <cuda_bf16.h>
#include <math.h>

#define HD 128
#define ETILE 128
#define NTILE 64
#define NMAX 20000
#define EMAX 640000

// ---------------- scratch (device globals: allocation-free)
__device__ float g_P[NMAX * HD];
__device__ float g_Q[NMAX * HD];
__device__ float g_mi[NMAX * HD];
__device__ float g_psum[NMAX * 3];
__device__ float g_cnt[NMAX];
// weight images: W2 as tf32 B-fragments (m16n8k8), C1 as bf16 B-fragments (m16n8k16)
__device__ __align__(16) float g_W2t[16384];            // 65536 B
__device__ __align__(16) unsigned char g_imgC1[32768];  // cW1^T bf16

// ---------------- helpers
__device__ __forceinline__ float silu(float x) {
    float hx = 0.5f * x;
    float t;
    asm("tanh.approx.f32 %0, %1;" : "=f"(t) : "f"(hx));
    return fmaf(hx, t, hx);
}

__device__ __forceinline__ unsigned smem_u32(const void* p) {
    unsigned r;
    asm("{ .reg .u64 t; cvta.to.shared.u64 t, %1; cvt.u32.u64 %0, t; }"
        : "=r"(r) : "l"(p));
    return r;
}

__device__ __forceinline__ void red_add_v2(float* p, float a, float b) {
    asm volatile("red.global.add.v2.f32 [%0], {%1, %2};"
                 :: "l"(p), "f"(a), "f"(b) : "memory");
}

__device__ __forceinline__ unsigned bfpack(__nv_bfloat16 a, __nv_bfloat16 b) {
    unsigned short ua = __bfloat16_as_ushort(a), ub = __bfloat16_as_ushort(b);
    return (unsigned)ua | ((unsigned)ub << 16);
}

__device__ __forceinline__ void bfsplit(float v, __nv_bfloat16& hi, __nv_bfloat16& lo) {
    hi = __float2bfloat16(v);
    lo = __float2bfloat16(v - __bfloat162float(hi));
}

// m16n8k16 row.col f32.bf16.bf16.f32 — standard PTX
__device__ __forceinline__ void mma_bf16(float* c, const uint4& a, const uint2& b) {
    asm volatile(
        "mma.sync.aligned.m16n8k16.row.col.f32.bf16.bf16.f32 "
        "{%0,%1,%2,%3}, {%4,%5,%6,%7}, {%8,%9}, {%0,%1,%2,%3};"
        : "+f"(c[0]), "+f"(c[1]), "+f"(c[2]), "+f"(c[3])
        : "r"(a.x), "r"(a.y), "r"(a.z), "r"(a.w), "r"(b.x), "r"(b.y));
}

// m16n8k8 row.col f32.tf32.tf32.f32 — standard PTX (fp32 bits as tf32 operands)
__device__ __forceinline__ void mma_tf32(float* c, const uint4& a, const uint2& b) {
    asm volatile(
        "mma.sync.aligned.m16n8k8.row.col.f32.tf32.tf32.f32 "
        "{%0,%1,%2,%3}, {%4,%5,%6,%7}, {%8,%9}, {%0,%1,%2,%3};"
        : "+f"(c[0]), "+f"(c[1]), "+f"(c[2]), "+f"(c[3])
        : "r"(a.x), "r"(a.y), "r"(a.z), "r"(a.w), "r"(b.x), "r"(b.y));
}

// SMEM layout
#define ABLK   528
#define SM_A   0                     // tf32 A image: 128 blocks x 528 = 67584
#define SM_W2  67584                 // 65536 (tf32 B fragments)
#define SM_C1  133120                // 32768 (bf16 B fragments)
#define SM_META 165888               // ~4KB
#define EDGE_SMEM 169984

// ---------------------------------------------------------------- zero
__global__ void zero_kernel(int N) {
    int i = blockIdx.x * blockDim.x + threadIdx.x;
    if (i < N * HD) g_mi[i] = 0.0f;
    int j = i - N * HD;
    if (j >= 0 && j < N * 3) g_psum[j] = 0.0f;
    int k = i - N * (HD + 3);
    if (k >= 0 && k < N) g_cnt[k] = 0.0f;
}

// ---------------------------------------------------------------- weight prep
// W2 (tf32 m16n8k8 B): slot = ((ni*16+ks)*32 + (n&7)*4+(k&3))*8 + ((k>>2)&1)*4
// C1 (bf16 m16n8k16 B): R13 layout
__global__ void prep_weights_kernel(const float* __restrict__ eW2,
                                    const float* __restrict__ cW1) {
    int i = blockIdx.x * blockDim.x + threadIdx.x;
    if (i >= HD * HD) return;
    int k = i >> 7, n = i & 127;
    {
        unsigned off2 = (((unsigned)(n >> 3) * 16u + (unsigned)(k >> 3)) * 32u
                         + (unsigned)((n & 7) * 4 + (k & 3))) * 8u
                      + (unsigned)(((k >> 2) & 1) * 4);
        *(float*)((unsigned char*)g_W2t + off2) = eW2[i];
    }
    {
        unsigned off = (((unsigned)(n >> 3) * 8u + (unsigned)(k >> 4)) * 32u
                        + (unsigned)((n & 7) * 4 + ((k & 7) >> 1))) * 8u
                     + (unsigned)(((k & 15) >> 3) * 4) + (unsigned)((k & 1) * 2);
        *(__nv_bfloat16*)(g_imgC1 + off) = __float2bfloat16(cW1[i]);
    }
}

// ---------------------------------------------------------------- node pre (R6)
__global__ __launch_bounds__(256) void node_pre_kernel(
    const float* __restrict__ h, const float* __restrict__ eW1, int N)
{
    __shared__ float sH[NTILE * HD];
    const int base = blockIdx.x * NTILE;

    for (int idx = threadIdx.x; idx < NTILE * HD; idx += 256) {
        int n = base + (idx >> 7);
        sH[idx] = (n < N) ? h[(size_t)n * HD + (idx & 127)] : 0.0f;
    }
    __syncthreads();

    const int lane = threadIdx.x & 31;
    const int warp = threadIdx.x >> 5;
    const int jj = lane * 4;
    const int e0 = warp * 8;

    #pragma unroll
    for (int half = 0; half < 2; half++) {
        const float* W = eW1 + (size_t)half * HD * HD;
        float* out = half ? g_Q : g_P;

        float acc[8][4];
        #pragma unroll
        for (int e = 0; e < 8; e++)
            #pragma unroll
            for (int i = 0; i < 4; i++) acc[e][i] = 0.f;

        for (int k = 0; k < HD; k += 4) {
            float4 w0 = *(const float4*)&W[(k + 0) * HD + jj];
            float4 w1 = *(const float4*)&W[(k + 1) * HD + jj];
            float4 w2 = *(const float4*)&W[(k + 2) * HD + jj];
            float4 w3 = *(const float4*)&W[(k + 3) * HD + jj];
            #pragma unroll
            for (int e = 0; e < 8; e++) {
                float4 tv = *(const float4*)&sH[(e0 + e) * HD + k];
                acc[e][0] = fmaf(tv.x, w0.x, acc[e][0]);
                acc[e][1] = fmaf(tv.x, w0.y, acc[e][1]);
                acc[e][2] = fmaf(tv.x, w0.z, acc[e][2]);
                acc[e][3] = fmaf(tv.x, w0.w, acc[e][3]);
                acc[e][0] = fmaf(tv.y, w1.x, acc[e][0]);
                acc[e][1] = fmaf(tv.y, w1.y, acc[e][1]);
                acc[e][2] = fmaf(tv.y, w1.z, acc[e][2]);
                acc[e][3] = fmaf(tv.y, w1.w, acc[e][3]);
                acc[e][0] = fmaf(tv.z, w2.x, acc[e][0]);
                acc[e][1] = fmaf(tv.z, w2.y, acc[e][1]);
                acc[e][2] = fmaf(tv.z, w2.z, acc[e][2]);
                acc[e][3] = fmaf(tv.z, w2.w, acc[e][3]);
                acc[e][0] = fmaf(tv.w, w3.x, acc[e][0]);
                acc[e][1] = fmaf(tv.w, w3.y, acc[e][1]);
                acc[e][2] = fmaf(tv.w, w3.z, acc[e][2]);
                acc[e][3] = fmaf(tv.w, w3.w, acc[e][3]);
            }
        }
        #pragma unroll
        for (int e = 0; e < 8; e++) {
            int n = base + e0 + e;
            if (n < N) {
                float4 o = make_float4(acc[e][0], acc[e][1], acc[e][2], acc[e][3]);
                *(float4*)&out[(size_t)n * HD + jj] = o;
            }
        }
    }
}

// ---------------------------------------------------------------- edge kernel
// Persistent, 512 threads (16 warps), 1 CTA/SM.
// Warp w: matom mA = w&7 (16 rows), col half nh = w>>3.
// GEMM1: tf32 single pass. GEMM2: bf16 (R13).
__global__ __launch_bounds__(512, 1) void edge_kernel(
    const float* __restrict__ pos,
    const int* __restrict__ eidx,
    const float* __restrict__ eW1, const float* __restrict__ eb1,
    const float* __restrict__ eb2,
    const float* __restrict__ cb1, const float* __restrict__ cW2,
    int N, int E, int numTiles)
{
    extern __shared__ __align__(16) unsigned char S[];

    const int tid  = threadIdx.x;
    const int w    = tid >> 5;
    const int lane = tid & 31;

    int*   sR  = (int*)(S + SM_META);
    int*   sC  = (int*)(S + SM_META + 512);
    float* sSq = (float*)(S + SM_META + 1024);
    float* sDx = (float*)(S + SM_META + 1536);
    float* sDy = (float*)(S + SM_META + 2048);
    float* sDz = (float*)(S + SM_META + 2560);
    float* sPart = (float*)(S + SM_META + 3072);  // [2][128]

    // stage weight images once
    {
        const uint4* a = (const uint4*)g_W2t;
        const uint4* b = (const uint4*)g_imgC1;
        uint4* wa = (uint4*)(S + SM_W2);
        uint4* wb = (uint4*)(S + SM_C1);
        for (int i = tid; i < 4096; i += 512) wa[i] = a[i];
        for (int i = tid; i < 2048; i += 512) wb[i] = b[i];
    }

    const float* w256 = eW1 + 256 * HD;

    // gather constants: warp per edge (8 edges/warp), lane = 4 consecutive cols
    const int gk = lane * 4;
    const float4 gW = __ldg((const float4*)&w256[gk]);
    const float4 gB = __ldg((const float4*)&eb1[gk]);
    const unsigned gKs = (unsigned)(gk >> 3);            // tf32 kstep (0..15)
    const unsigned gRegC2 = (unsigned)(((gk >> 2) & 1) * 2);  // reg col offset

    // mma tile mapping
    const int mA = w & 7;              // matom (16 rows)
    const int nh = w >> 3;             // col half
    const int nA0 = nh * 8;            // first natom
    const int rowT = lane >> 2;
    const int colJ = (lane & 3) * 2;

    for (int t = blockIdx.x; t < numTiles; t += gridDim.x) {
        const int base = t * ETILE;
        __syncthreads();   // protect SMEM reuse across tiles

        if (tid < ETILE) {
            int e = base + tid;
            int r = eidx[e];
            int c = eidx[E + e];
            float dx = pos[r * 3 + 0] - pos[c * 3 + 0];
            float dy = pos[r * 3 + 1] - pos[c * 3 + 1];
            float dz = pos[r * 3 + 2] - pos[c * 3 + 2];
            sR[tid] = r; sC[tid] = c;
            sSq[tid] = dx * dx + dy * dy + dz * dz;
            sDx[tid] = dx; sDy[tid] = dy; sDz[tid] = dz;
        }
        __syncthreads();

        // ---- gather: warp per edge (coalesced), silu, store fp32 tf32-fragment slots
        #pragma unroll 4
        for (int it = 0; it < 8; it++) {
            int e = w * 8 + it;
            int r = sR[e], c = sC[e];
            float sq = sSq[e];
            float4 P = __ldg((const float4*)&g_P[(size_t)r * HD + gk]);
            float4 Q = __ldg((const float4*)&g_Q[(size_t)c * HD + gk]);
            float v0 = silu(P.x + Q.x + sq * gW.x + gB.x);
            float v1 = silu(P.y + Q.y + sq * gW.y + gB.y);
            float v2 = silu(P.z + Q.z + sq * gW.z + gB.z);
            float v3 = silu(P.w + Q.w + sq * gW.w + gB.w);
            int matom = e >> 4, eloc = e & 15;
            unsigned b0 = SM_A + ((unsigned)(matom * 16) + gKs) * ABLK
                        + (unsigned)((eloc & 7) * 4) * 16u
                        + ((unsigned)(eloc >> 3) + gRegC2) * 4u;
            *(float*)(S + b0)      = v0;
            *(float*)(S + b0 + 16) = v1;
            *(float*)(S + b0 + 32) = v2;
            *(float*)(S + b0 + 48) = v3;
        }
        __syncthreads();

        // ---- GEMM1: 16x64 per warp, tf32 single pass over K=128 (16 ksteps)
        float acc[8][4];
        #pragma unroll
        for (int ni = 0; ni < 8; ni++)
            #pragma unroll
            for (int q = 0; q < 4; q++) acc[ni][q] = 0.f;

        #pragma unroll
        for (int ks = 0; ks < 16; ks++) {
            uint4 a0 = *(const uint4*)(S + SM_A
                      + (mA * 16 + ks) * ABLK + lane * 16);
            uint2 bv[8];
            #pragma unroll
            for (int ni = 0; ni < 8; ni++)
                bv[ni] = *(const uint2*)(S + SM_W2
                         + (((nA0 + ni) * 16 + ks) * 32 + lane) * 8);
            #pragma unroll
            for (int ni = 0; ni < 8; ni++)
                mma_tf32(acc[ni], a0, bv[ni]);
        }

        // ---- epilogue 1: m = silu(D1 + eb2); scatter; stash packed bf16
        unsigned stash[8][2];
        {
            int e0r = mA * 16 + rowT;
            size_t rb0 = (size_t)sR[e0r] * HD;
            size_t rb1 = (size_t)sR[e0r + 8] * HD;
            #pragma unroll
            for (int ni = 0; ni < 8; ni++) {
                int n = nh * 64 + ni * 8 + colJ;
                float m00 = silu(acc[ni][0] + __ldg(&eb2[n]));
                float m01 = silu(acc[ni][1] + __ldg(&eb2[n + 1]));
                float m10 = silu(acc[ni][2] + __ldg(&eb2[n]));
                float m11 = silu(acc[ni][3] + __ldg(&eb2[n + 1]));
                red_add_v2(&g_mi[rb0 + n], m00, m01);
                red_add_v2(&g_mi[rb1 + n], m10, m11);
                stash[ni][0] = bfpack(__float2bfloat16(m00), __float2bfloat16(m01));
                stash[ni][1] = bfpack(__float2bfloat16(m10), __float2bfloat16(m11));
            }
        }
        __syncthreads();   // all GEMM1 reads of A image complete

        // repack M into A image (bf16 m16n8k16 layout) for GEMM2
        #pragma unroll
        for (int ni = 0; ni < 8; ni++) {
            unsigned kstepD = (unsigned)(nh * 4 + (ni >> 1));
            unsigned slotB = ((unsigned)(mA * 8) + kstepD) * ABLK
                           + (unsigned)lane * 16u;
            unsigned regLo = (unsigned)((ni & 1) << 1);
            *(unsigned*)(S + SM_A + slotB + regLo * 4u)        = stash[ni][0];
            *(unsigned*)(S + SM_A + slotB + (regLo + 1u) * 4u) = stash[ni][1];
        }
        __syncthreads();

        // ---- GEMM2: D2 = M @ cW1 (single bf16 pass)
        #pragma unroll
        for (int ni = 0; ni < 8; ni++)
            #pragma unroll
            for (int q = 0; q < 4; q++) acc[ni][q] = 0.f;

        #pragma unroll
        for (int ks = 0; ks < 8; ks++) {
            uint4 a0 = *(const uint4*)(S + SM_A
                      + (mA * 8 + ks) * ABLK + lane * 16);
            uint2 bv[8];
            #pragma unroll
            for (int ni = 0; ni < 8; ni++)
                bv[ni] = *(const uint2*)(S + SM_C1
                         + (((nA0 + ni) * 8 + ks) * 32 + lane) * 8);
            #pragma unroll
            for (int ni = 0; ni < 8; ni++)
                mma_bf16(acc[ni], a0, bv[ni]);
        }

        // ---- epilogue 2: cw partial = silu(D2 + cb1) . cW2
        {
            float s0 = 0.f, s1 = 0.f;
            #pragma unroll
            for (int ni = 0; ni < 8; ni++) {
                int n = nh * 64 + ni * 8 + colJ;
                float cb0 = __ldg(&cb1[n]),  cb1v = __ldg(&cb1[n + 1]);
                float cw0 = __ldg(&cW2[n]),  cw1v = __ldg(&cW2[n + 1]);
                s0 += silu(acc[ni][0] + cb0) * cw0
                    + silu(acc[ni][1] + cb1v) * cw1v;
                s1 += silu(acc[ni][2] + cb0) * cw0
                    + silu(acc[ni][3] + cb1v) * cw1v;
            }
            s0 += __shfl_xor_sync(0xFFFFFFFFu, s0, 1);
            s0 += __shfl_xor_sync(0xFFFFFFFFu, s0, 2);
            s1 += __shfl_xor_sync(0xFFFFFFFFu, s1, 1);
            s1 += __shfl_xor_sync(0xFFFFFFFFu, s1, 2);
            if ((lane & 3) == 0) {
                int e0r = mA * 16 + rowT;
                sPart[nh * 128 + e0r]     = s0;
                sPart[nh * 128 + e0r + 8] = s1;
            }
        }
        __syncthreads();

        if (tid < ETILE) {
            float cw = sPart[tid] + sPart[128 + tid];
            float inv = rsqrtf(sSq[tid] + 1e-8f);
            float wgt = cw * inv;
            int r = sR[tid];
            atomicAdd(&g_psum[r * 3 + 0], sDx[tid] * wgt);
            atomicAdd(&g_psum[r * 3 + 1], sDy[tid] * wgt);
            atomicAdd(&g_psum[r * 3 + 2], sDz[tid] * wgt);
            atomicAdd(&g_cnt[r], 1.0f);
        }
    }
}

// ---------------------------------------------------------------- node out (R6, f32x2)
__device__ __forceinline__ void fma2(unsigned long long& acc,
                                     unsigned long long a, unsigned long long b) {
    asm("fma.rn.f32x2 %0, %1, %2, %0;" : "+l"(acc) : "l"(a), "l"(b));
}
__device__ __forceinline__ unsigned long long dup2(float x) {
    unsigned long long r;
    asm("mov.b64 %0, {%1, %1};" : "=l"(r) : "f"(x));
    return r;
}
__device__ __forceinline__ void lds_v2u64(unsigned long long& a, unsigned long long& b,
                                          unsigned addr) {
    asm volatile("ld.shared.v2.b64 {%0, %1}, [%2];" : "=l"(a), "=l"(b) : "r"(addr));
}
__device__ __forceinline__ float f2lo(unsigned long long v) {
    return __uint_as_float((unsigned)(v & 0xFFFFFFFFull));
}
__device__ __forceinline__ float f2hi(unsigned long long v) {
    return __uint_as_float((unsigned)(v >> 32));
}

__global__ __launch_bounds__(128) void node_out_kernel(
    const float* __restrict__ h, const float* __restrict__ pos,
    const float* __restrict__ nW1, const float* __restrict__ nb1,
    const float* __restrict__ nW2, const float* __restrict__ nb2,
    float* __restrict__ outH, float* __restrict__ outP, int N)
{
    __shared__ __align__(16) float2 sXp[16 * 2 * HD];

    const int base = blockIdx.x * 32;
    const int tid = threadIdx.x;

    for (int idx = tid; idx < 16 * (2 * HD / 4); idx += 128) {
        int p = idx >> 6, kg = idx & 63, k = kg << 2;
        int n0 = base + 2 * p, n1 = n0 + 1;
        float4 a, b;
        if (k < HD) {
            a = __ldg((const float4*)&h[(size_t)n0 * HD + k]);
            b = __ldg((const float4*)&h[(size_t)n1 * HD + k]);
        } else {
            a = *(const float4*)&g_mi[(size_t)n0 * HD + (k - HD)];
            b = *(const float4*)&g_mi[(size_t)n1 * HD + (k - HD)];
        }
        *(float4*)&sXp[p * 2 * HD + k]     = make_float4(a.x, b.x, a.y, b.y);
        *(float4*)&sXp[p * 2 * HD + k + 2] = make_float4(a.z, b.z, a.w, b.w);
    }
    __syncthreads();

    const int lane = tid & 31;
    const int warp = tid >> 5;
    const int jj = lane * 4;
    const int p0 = warp * 4;
    const unsigned x0 = smem_u32(sXp) + (unsigned)(p0 * 2 * HD) * 8u;

    {
        unsigned long long acc[4][4];
        #pragma unroll
        for (int p = 0; p < 4; p++)
            #pragma unroll
            for (int c = 0; c < 4; c++) acc[p][c] = 0ull;

        #pragma unroll 2
        for (int kk = 0; kk < 2 * HD; kk += 2) {
            float4 wA = __ldg((const float4*)&nW1[(kk + 0) * HD + jj]);
            float4 wB = __ldg((const float4*)&nW1[(kk + 1) * HD + jj]);
            unsigned long long wa0 = dup2(wA.x), wa1 = dup2(wA.y),
                               wa2 = dup2(wA.z), wa3 = dup2(wA.w);
            unsigned long long wb0 = dup2(wB.x), wb1 = dup2(wB.y),
                               wb2 = dup2(wB.z), wb3 = dup2(wB.w);
            #pragma unroll
            for (int p = 0; p < 4; p++) {
                unsigned long long t0, t1;
                lds_v2u64(t0, t1, x0 + (unsigned)(p * 2 * HD + kk) * 8u);
                fma2(acc[p][0], t0, wa0);
                fma2(acc[p][1], t0, wa1);
                fma2(acc[p][2], t0, wa2);
                fma2(acc[p][3], t0, wa3);
                fma2(acc[p][0], t1, wb0);
                fma2(acc[p][1], t1, wb1);
                fma2(acc[p][2], t1, wb2);
                fma2(acc[p][3], t1, wb3);
            }
        }
        __syncwarp();
        float4 b1 = *(const float4*)&nb1[jj];
        float bv[4] = { b1.x, b1.y, b1.z, b1.w };
        #pragma unroll
        for (int p = 0; p < 4; p++) {
            float4 A = make_float4(silu(f2lo(acc[p][0]) + bv[0]),
                                   silu(f2hi(acc[p][0]) + bv[0]),
                                   silu(f2lo(acc[p][1]) + bv[1]),
                                   silu(f2hi(acc[p][1]) + bv[1]));
            float4 B = make_float4(silu(f2lo(acc[p][2]) + bv[2]),
                                   silu(f2hi(acc[p][2]) + bv[2]),
                                   silu(f2lo(acc[p][3]) + bv[3]),
                                   silu(f2hi(acc[p][3]) + bv[3]));
            *(float4*)&sXp[(p0 + p) * 2 * HD + jj]     = A;
            *(float4*)&sXp[(p0 + p) * 2 * HD + jj + 2] = B;
        }
    }
    __syncwarp();

    {
        unsigned long long acc[4][4];
        #pragma unroll
        for (int p = 0; p < 4; p++)
            #pragma unroll
            for (int c = 0; c < 4; c++) acc[p][c] = 0ull;

        #pragma unroll 2
        for (int kk = 0; kk < HD; kk += 2) {
            float4 wA = __ldg((const float4*)&nW2[(kk + 0) * HD + jj]);
            float4 wB = __ldg((const float4*)&nW2[(kk + 1) * HD + jj]);
            unsigned long long wa0 = dup2(wA.x), wa1 = dup2(wA.y),
                               wa2 = dup2(wA.z), wa3 = dup2(wA.w);
            unsigned long long wb0 = dup2(wB.x), wb1 = dup2(wB.y),
                               wb2 = dup2(wB.z), wb3 = dup2(wB.w);
            #pragma unroll
            for (int p = 0; p < 4; p++) {
                unsigned long long t0, t1;
                lds_v2u64(t0, t1, x0 + (unsigned)(p * 2 * HD + kk) * 8u);
                fma2(acc[p][0], t0, wa0);
                fma2(acc[p][1], t0, wa1);
                fma2(acc[p][2], t0, wa2);
                fma2(acc[p][3], t0, wa3);
                fma2(acc[p][0], t1, wb0);
                fma2(acc[p][1], t1, wb1);
                fma2(acc[p][2], t1, wb2);
                fma2(acc[p][3], t1, wb3);
            }
        }
        float4 b2 = *(const float4*)&nb2[jj];
        #pragma unroll
        for (int p = 0; p < 4; p++) {
            int n0 = base + 2 * (p0 + p), n1 = n0 + 1;
            float4 h0 = __ldg((const float4*)&h[(size_t)n0 * HD + jj]);
            float4 h1 = __ldg((const float4*)&h[(size_t)n1 * HD + jj]);
            float4 o0 = make_float4(h0.x + f2lo(acc[p][0]) + b2.x,
                                    h0.y + f2lo(acc[p][1]) + b2.y,
                                    h0.z + f2lo(acc[p][2]) + b2.z,
                                    h0.w + f2lo(acc[p][3]) + b2.w);
            float4 o1 = make_float4(h1.x + f2hi(acc[p][0]) + b2.x,
                                    h1.y + f2hi(acc[p][1]) + b2.y,
                                    h1.z + f2hi(acc[p][2]) + b2.z,
                                    h1.w + f2hi(acc[p][3]) + b2.w);
            *(float4*)&outH[(size_t)n0 * HD + jj] = o0;
            *(float4*)&outH[(size_t)n1 * HD + jj] = o1;
        }
    }

    if (tid < 32) {
        int n = base + tid;
        float c = fmaxf(g_cnt[n], 1.0f);
        outP[n * 3 + 0] = pos[n * 3 + 0] + g_psum[n * 3 + 0] / c;
        outP[n * 3 + 1] = pos[n * 3 + 1] + g_psum[n * 3 + 1] / c;
        outP[n * 3 + 2] = pos[n * 3 + 2] + g_psum[n * 3 + 2] / c;
    }
}

// ---------------------------------------------------------------- launch
extern "C" void kernel_launch(void* const* d_in, const int* in_sizes, int n_in,
                              void* d_out, int out_size)
{
    const float* h    = (const float*)d_in[0];
    const float* pos  = (const float*)d_in[1];
    const int*   eidx = (const int*)d_in[2];
    const float* eW1  = (const float*)d_in[3];
    const float* eb1  = (const float*)d_in[4];
    const float* eW2  = (const float*)d_in[5];
    const float* eb2  = (const float*)d_in[6];
    const float* cW1  = (const float*)d_in[7];
    const float* cb1  = (const float*)d_in[8];
    const float* cW2  = (const float*)d_in[9];
    const float* nW1  = (const float*)d_in[10];
    const float* nb1  = (const float*)d_in[11];
    const float* nW2  = (const float*)d_in[12];
    const float* nb2  = (const float*)d_in[13];

    const int N = in_sizes[0] / HD;
    const int E = in_sizes[2] / 2;

    float* outH = (float*)d_out;
    float* outP = outH + (size_t)N * HD;

    cudaFuncSetAttribute(edge_kernel, cudaFuncAttributeMaxDynamicSharedMemorySize,
                         EDGE_SMEM);

    zero_kernel<<<(N * (HD + 4) + 255) / 256, 256>>>(N);
    prep_weights_kernel<<<(HD * HD + 255) / 256, 256>>>(eW2, cW1);
    node_pre_kernel<<<(N + NTILE - 1) / NTILE, 256>>>(h, eW1, N);
    edge_kernel<<<152, 512, EDGE_SMEM>>>(pos, eidx, eW1, eb1, eb2, cb1, cW2,
                                         N, E, E / ETILE);
    node_out_kernel<<<N / 32, 128>>>(h, pos, nW1, nb1, nW2, nb2, outH, outP, N);
}